// round 13
// baseline (speedup 1.0000x reference)
#include <cuda_runtime.h>
#include <cuda_fp16.h>
#include <cstdint>

#define BATCH 2
#define SEQ   2048
#define DIM   1024
#define HEADS 16
#define HDIM  64
#define SCALE 0.125f
#define MTOT  4096
#define GPITCH 72
#define CPITCH 72

typedef __half h16;

// ---------------- scratch ----------------
__device__ float g_partial[BATCH * 32 * DIM];
__device__ float g_xavg[BATCH * DIM];
__device__ float g_kavg[BATCH * DIM];
__device__ float g_u[BATCH * HEADS * DIM];
__device__ float g_z[BATCH * HEADS * SEQ];

__device__ h16 g_xhi[(size_t)MTOT * DIM];
__device__ h16 g_wvhi[DIM * DIM];
__device__ h16 g_wphi[DIM * DIM];
__device__ h16 g_vthi[32 * HDIM * SEQ];
__device__ h16 g_a2hi[32 * 4224];
__device__ h16 g_ohhi[(size_t)MTOT * DIM];

// ---------------- PTX helpers ----------------
__device__ __forceinline__ unsigned smem_u32(const void* p) {
    return (unsigned)__cvta_generic_to_shared(p);
}

__device__ __forceinline__ void ldsm_x4(unsigned& r0, unsigned& r1, unsigned& r2, unsigned& r3, unsigned a) {
    asm volatile("ldmatrix.sync.aligned.m8n8.x4.shared.b16 {%0,%1,%2,%3}, [%4];"
                 : "=r"(r0), "=r"(r1), "=r"(r2), "=r"(r3) : "r"(a));
}

__device__ __forceinline__ void mma_f16(float* c, unsigned a0, unsigned a1, unsigned a2, unsigned a3,
                                        unsigned b0, unsigned b1) {
    asm volatile("mma.sync.aligned.m16n8k16.row.col.f32.f16.f16.f32 "
                 "{%0,%1,%2,%3}, {%4,%5,%6,%7}, {%8,%9}, {%0,%1,%2,%3};"
                 : "+f"(c[0]), "+f"(c[1]), "+f"(c[2]), "+f"(c[3])
                 : "r"(a0), "r"(a1), "r"(a2), "r"(a3), "r"(b0), "r"(b1));
}

// fp16-accumulate variant: 2x rate on legacy tensor path
__device__ __forceinline__ void mma_f16acc(unsigned* c, unsigned a0, unsigned a1, unsigned a2, unsigned a3,
                                           unsigned b0, unsigned b1) {
    asm volatile("mma.sync.aligned.m16n8k16.row.col.f16.f16.f16.f16 "
                 "{%0,%1}, {%2,%3,%4,%5}, {%6,%7}, {%0,%1};"
                 : "+r"(c[0]), "+r"(c[1])
                 : "r"(a0), "r"(a1), "r"(a2), "r"(a3), "r"(b0), "r"(b1));
}

// ---------------- fused x split + partial column sums ----------------
__global__ void splitx_colsum(const float* __restrict__ x) {
    int c = blockIdx.x * 256 + threadIdx.x;
    int b = blockIdx.y, sz = blockIdx.z;
    const float* xp = x + ((size_t)b * SEQ + (size_t)sz * 64) * DIM + c;
    h16* hp = g_xhi + ((size_t)b * SEQ + (size_t)sz * 64) * DIM + c;
    float sum = 0.f;
    #pragma unroll 8
    for (int n = 0; n < 64; n++) {
        float v = xp[(size_t)n * DIM];
        sum += v;
        hp[(size_t)n * DIM] = __float2half_rn(v);
    }
    g_partial[(b * 32 + sz) * DIM + c] = sum;
}

__global__ void colsum_final() {
    int w = (blockIdx.x * 256 + threadIdx.x) >> 5;
    int lane = threadIdx.x & 31;
    int b = w >> 10, c = w & (DIM - 1);
    float s = g_partial[(b * 32 + lane) * DIM + c];
    #pragma unroll
    for (int o = 16; o > 0; o >>= 1) s += __shfl_xor_sync(0xffffffffu, s, o);
    if (lane == 0) g_xavg[b * DIM + c] = s * (1.0f / SEQ);
}

__global__ void kavg_kernel(const float* __restrict__ wk) {
    int w = (blockIdx.x * blockDim.x + threadIdx.x) >> 5;
    int lane = threadIdx.x & 31;
    int b = w / DIM, co = w % DIM;
    const float* wr = wk + (size_t)co * DIM;
    const float* xa = g_xavg + b * DIM;
    float s = 0.f;
    #pragma unroll 4
    for (int c = lane; c < DIM; c += 32) s += wr[c] * xa[c];
    #pragma unroll
    for (int o = 16; o > 0; o >>= 1) s += __shfl_xor_sync(0xffffffffu, s, o);
    if (lane == 0) g_kavg[b * DIM + co] = s;
}

__global__ void u_kernel(const float* __restrict__ wq) {
    int c = blockIdx.x * 256 + threadIdx.x;
    int h = blockIdx.y, b = blockIdx.z;
    __shared__ float ka[HDIM];
    if (threadIdx.x < HDIM) ka[threadIdx.x] = g_kavg[b * DIM + h * HDIM + threadIdx.x];
    __syncthreads();
    float s = 0.f;
    #pragma unroll
    for (int d = 0; d < HDIM; d++) s += ka[d] * wq[(size_t)(h * HDIM + d) * DIM + c];
    g_u[(b * HEADS + h) * DIM + c] = s;
}

__global__ __launch_bounds__(256) void z_kernel2() {
    __shared__ float us[HEADS][136];
    int tid = threadIdx.x, lane = tid & 31, w = tid >> 5;
    int row = blockIdx.x * 8 + w;
    int b = row >> 11;
    int n = row & (SEQ - 1);
    const __half2* xr = (const __half2*)(g_xhi + (size_t)row * DIM);
    const float* ub = g_u + (size_t)b * HEADS * DIM;

    float acc[HEADS];
    #pragma unroll
    for (int h = 0; h < HEADS; h++) acc[h] = 0.f;

    for (int kc = 0; kc < DIM; kc += 128) {
        for (int t = tid; t < HEADS * 128; t += 256) {
            us[t >> 7][t & 127] = ub[(t >> 7) * DIM + kc + (t & 127)];
        }
        __syncthreads();
        __half2 x01 = xr[(kc >> 1) + lane * 2];
        __half2 x23 = xr[(kc >> 1) + lane * 2 + 1];
        float2 f01 = __half22float2(x01);
        float2 f23 = __half22float2(x23);
        #pragma unroll
        for (int h = 0; h < HEADS; h++) {
            float4 uv = *(const float4*)&us[h][lane * 4];
            acc[h] += f01.x * uv.x + f01.y * uv.y + f23.x * uv.z + f23.y * uv.w;
        }
        __syncthreads();
    }
    #pragma unroll
    for (int h = 0; h < HEADS; h++) {
        float s = acc[h];
        #pragma unroll
        for (int o = 16; o > 0; o >>= 1) s += __shfl_xor_sync(0xffffffffu, s, o);
        if (lane == 0) g_z[((size_t)(b * HEADS + h)) * SEQ + n] = s * SCALE;
    }
}

__global__ void softmax_attn2() {
    int bh = blockIdx.x;
    float* z = g_z + (size_t)bh * SEQ;
    __shared__ float red[256];
    int t = threadIdx.x;
    float m = -1e30f;
    for (int i = t; i < SEQ; i += 256) m = fmaxf(m, z[i]);
    red[t] = m; __syncthreads();
    for (int o = 128; o > 0; o >>= 1) { if (t < o) red[t] = fmaxf(red[t], red[t + o]); __syncthreads(); }
    m = red[0]; __syncthreads();
    float s = 0.f;
    for (int i = t; i < SEQ; i += 256) { float e = __expf(z[i] - m); z[i] = e; s += e; }
    red[t] = s; __syncthreads();
    for (int o = 128; o > 0; o >>= 1) { if (t < o) red[t] += red[t + o]; __syncthreads(); }
    float inv = 1.0f / red[0];
    for (int i = t; i < SEQ; i += 256) z[i] *= inv;
    __syncthreads();
    for (int i = t; i < 4224; i += 256) {
        g_a2hi[bh * 4224 + i] = __float2half_rn(z[i & (SEQ - 1)]);
    }
}

// both weight splits in one launch (blockIdx.y selects)
__global__ void split_w(const float* __restrict__ wv, const float* __restrict__ wp) {
    int i = blockIdx.x * 256 + threadIdx.x;
    const float* in = blockIdx.y ? wp : wv;
    h16* hi = blockIdx.y ? g_wphi : g_wvhi;
    float4 v = ((const float4*)in)[i];
    __half2* H = (__half2*)hi;
    H[i * 2 + 0] = __halves2half2(__float2half_rn(v.x), __float2half_rn(v.y));
    H[i * 2 + 1] = __halves2half2(__float2half_rn(v.z), __float2half_rn(v.w));
}

// ---------------- fp16 tensor GEMM: BK=64, cp.async 3-stage, prefetch distance 2 ----------------
#define GSTAGE (128 * GPITCH)
__global__ __launch_bounds__(256, 2) void gemm_split(
    const h16* __restrict__ Ahi, const h16* __restrict__ Whi,
    const float* __restrict__ bias, float* __restrict__ C, int mode)
{
    extern __shared__ h16 gsm[];
    h16* As_ = gsm;
    h16* Bs_ = gsm + 3 * GSTAGE;
    const int tid = threadIdx.x;
    const int lane = tid & 31;
    const int wid = tid >> 5;
    const int m0 = blockIdx.y * 128;
    const int n0 = blockIdx.x * 128;
    const int wm = (wid >> 2) * 64;
    const int wn = (wid & 3) * 32;
    const int g = lane >> 2;
    const int t4 = lane & 3;

    float acc[4][4][4];
    #pragma unroll
    for (int i = 0; i < 4; i++)
        #pragma unroll
        for (int j = 0; j < 4; j++)
            #pragma unroll
            for (int k = 0; k < 4; k++) acc[i][j][k] = 0.f;

    const int arow = wm + (lane & 15);
    const int acolsel = (lane >> 4) * 8;
    const int bgrp = lane >> 3;
    const int brow = wn + ((bgrp >> 1) * 8) + (lane & 7);
    const int bcolsel = (bgrp & 1) * 8;

    const int lr = tid >> 3;
    const int lc16 = (tid & 7) * 8;

#define G_ISSUE(st_, s_) do {                                                            \
    const int kk_ = (s_) * 64;                                                           \
    _Pragma("unroll")                                                                    \
    for (int rq_ = 0; rq_ < 4; rq_++) {                                                  \
        const int row_ = lr + rq_ * 32;                                                  \
        unsigned sa_ = smem_u32(As_ + (st_) * GSTAGE + row_ * GPITCH + lc16);            \
        const h16* ga_ = Ahi + (size_t)(m0 + row_) * DIM + kk_ + lc16;                   \
        asm volatile("cp.async.cg.shared.global [%0], [%1], 16;" :: "r"(sa_), "l"(ga_)); \
        unsigned sb_ = smem_u32(Bs_ + (st_) * GSTAGE + row_ * GPITCH + lc16);            \
        const h16* gb_ = Whi + (size_t)(n0 + row_) * DIM + kk_ + lc16;                   \
        asm volatile("cp.async.cg.shared.global [%0], [%1], 16;" :: "r"(sb_), "l"(gb_)); \
    }                                                                                    \
    asm volatile("cp.async.commit_group;");                                              \
} while (0)

    G_ISSUE(0, 0);
    G_ISSUE(1, 1);

    for (int s = 0; s < 16; s++) {
        const int st = s % 3;
        if (s + 1 < 16) {
            asm volatile("cp.async.wait_group 1;");
        } else {
            asm volatile("cp.async.wait_group 0;");
        }
        __syncthreads();
        const h16* Ab = As_ + st * GSTAGE;
        const h16* Bb = Bs_ + st * GSTAGE;
        #pragma unroll
        for (int khb = 0; khb < 64; khb += 16) {
            unsigned af[4][4];
            #pragma unroll
            for (int mi = 0; mi < 4; mi++) {
                ldsm_x4(af[mi][0], af[mi][1], af[mi][2], af[mi][3],
                        smem_u32(Ab + (arow + mi * 16) * GPITCH + khb + acolsel));
            }
            unsigned bfr[4][2];
            #pragma unroll
            for (int p = 0; p < 2; p++) {
                unsigned r0, r1, r2, r3;
                ldsm_x4(r0, r1, r2, r3,
                        smem_u32(Bb + (brow + p * 16) * GPITCH + khb + bcolsel));
                bfr[p * 2 + 0][0] = r0; bfr[p * 2 + 0][1] = r1;
                bfr[p * 2 + 1][0] = r2; bfr[p * 2 + 1][1] = r3;
            }
            #pragma unroll
            for (int mi = 0; mi < 4; mi++)
                #pragma unroll
                for (int ni = 0; ni < 4; ni++)
                    mma_f16(acc[mi][ni], af[mi][0], af[mi][1], af[mi][2], af[mi][3],
                            bfr[ni][0], bfr[ni][1]);
        }
        if (s + 2 < 16) G_ISSUE((s + 2) % 3, s + 2);
    }
#undef G_ISSUE

    if (mode == 0) {
        #pragma unroll
        for (int mi = 0; mi < 4; mi++) {
            int row = m0 + wm + mi * 16 + g;
            #pragma unroll
            for (int ni = 0; ni < 4; ni++) {
                int col = n0 + wn + ni * 8 + 2 * t4;
                float2 bb = *(const float2*)&bias[col];
                float2 v0 = make_float2(acc[mi][ni][0] + bb.x, acc[mi][ni][1] + bb.y);
                float2 v1 = make_float2(acc[mi][ni][2] + bb.x, acc[mi][ni][3] + bb.y);
                *(float2*)&C[(size_t)row * DIM + col] = v0;
                *(float2*)&C[(size_t)(row + 8) * DIM + col] = v1;
            }
        }
    } else {
        #pragma unroll
        for (int mi = 0; mi < 4; mi++) {
            int row = m0 + wm + mi * 16 + g;
            int b = row >> 11;
            int j = row & (SEQ - 1);
            #pragma unroll
            for (int ni = 0; ni < 4; ni++) {
                int col = n0 + wn + ni * 8 + 2 * t4;
                #pragma unroll
                for (int q = 0; q < 4; q++) {
                    int cc = col + (q & 1);
                    int jj = j + (q >> 1) * 8;
                    size_t idx = (((size_t)(b * HEADS + (cc >> 6))) * HDIM + (cc & 63)) * SEQ + jj;
                    g_vthi[idx] = __float2half_rn(acc[mi][ni][q]);
                }
            }
        }
    }
}

// ---------------- fp16 circular conv, i-tile 256, BK=64, fp16-accum with per-chunk f32 flush ----------------
__global__ __launch_bounds__(256) void conv_mma() {
    __shared__ unsigned wps[2][320];
    __shared__ h16 Bs[2][64 * CPITCH];
    const int tid = threadIdx.x;
    const int lane = tid & 31;
    const int wid = tid >> 5;
    const int i0 = blockIdx.x * 256;
    const int bh = blockIdx.y;
    const int b = bh >> 4;
    const int h = bh & 15;
    const int wm = (wid >> 1) * 64;
    const int wn = (wid & 1) * 32;
    const int g = lane >> 2;
    const int t4 = lane & 3;

    const unsigned short* a2h = (const unsigned short*)(g_a2hi + (size_t)bh * 4224);
    const h16* vth = g_vthi + (size_t)bh * HDIM * SEQ;

    float acc[4][4][4];
    unsigned acc16[4][4][2];
    #pragma unroll
    for (int i = 0; i < 4; i++)
        #pragma unroll
        for (int j = 0; j < 4; j++) {
            #pragma unroll
            for (int k = 0; k < 4; k++) acc[i][j][k] = 0.f;
            acc16[i][j][0] = 0u; acc16[i][j][1] = 0u;
        }

    const int br0 = tid >> 3;
    const int bc16 = (tid & 7) * 8;
    const int bgrp = lane >> 3;
    const int brow = wn + ((bgrp >> 1) * 8) + (lane & 7);
    const int bcolsel = (bgrp & 1) * 8;

    {
        const int ws = 1793 - i0;
        wps[0][tid] = (unsigned)a2h[ws + tid] | ((unsigned)a2h[ws + tid + 1] << 16);
        if (tid < 64) {
            int t2 = tid + 256;
            wps[0][t2] = (unsigned)a2h[ws + t2] | ((unsigned)a2h[ws + t2 + 1] << 16);
        }
        uint4 pb0 = *(const uint4*)(vth + (size_t)br0 * SEQ + bc16);
        uint4 pb1 = *(const uint4*)(vth + (size_t)(br0 + 32) * SEQ + bc16);
        *(uint4*)&Bs[0][br0 * CPITCH + bc16] = pb0;
        *(uint4*)&Bs[0][(br0 + 32) * CPITCH + bc16] = pb1;
    }
    __syncthreads();

    for (int s = 0; s < 32; s++) {
        const int buf = s & 1;
        const int sn = s + 1;
        unsigned wv0 = 0u, wv1 = 0u;
        uint4 bv0, bv1;
        if (sn < 32) {
            const int j0 = sn * 64;
            const int ws = 1793 + j0 - i0;
            wv0 = (unsigned)a2h[ws + tid] | ((unsigned)a2h[ws + tid + 1] << 16);
            if (tid < 64) {
                int t2 = tid + 256;
                wv1 = (unsigned)a2h[ws + t2] | ((unsigned)a2h[ws + t2 + 1] << 16);
            }
            bv0 = *(const uint4*)(vth + (size_t)br0 * SEQ + j0 + bc16);
            bv1 = *(const uint4*)(vth + (size_t)(br0 + 32) * SEQ + j0 + bc16);
        }
        #pragma unroll
        for (int khb = 0; khb < 64; khb += 16) {
            const int ub = 255 - (wm + g) + 2 * t4 + khb;
            unsigned fa0[4], fa1[4], fa2[4];
            #pragma unroll
            for (int mi = 0; mi < 4; mi++) {
                const int u = ub - mi * 16;
                fa0[mi] = wps[buf][u];
                fa1[mi] = wps[buf][u - 8];
                fa2[mi] = wps[buf][u + 8];
            }
            unsigned bfr[4][2];
            #pragma unroll
            for (int p = 0; p < 2; p++) {
                unsigned r0, r1, r2, r3;
                ldsm_x4(r0, r1, r2, r3,
                        smem_u32(&Bs[buf][(brow + p * 16) * CPITCH + khb + bcolsel]));
                bfr[p * 2 + 0][0] = r0; bfr[p * 2 + 0][1] = r1;
                bfr[p * 2 + 1][0] = r2; bfr[p * 2 + 1][1] = r3;
            }
            #pragma unroll
            for (int mi = 0; mi < 4; mi++)
                #pragma unroll
                for (int ni = 0; ni < 4; ni++)
                    mma_f16acc(acc16[mi][ni], fa0[mi], fa1[mi], fa2[mi], fa0[mi],
                               bfr[ni][0], bfr[ni][1]);
        }
        // flush fp16 chunk accumulators into fp32 (attn near-uniform => chunk partials small)
        #pragma unroll
        for (int mi = 0; mi < 4; mi++)
            #pragma unroll
            for (int ni = 0; ni < 4; ni++) {
                float2 f0 = __half22float2(*(__half2*)&acc16[mi][ni][0]);
                float2 f1 = __half22float2(*(__half2*)&acc16[mi][ni][1]);
                acc[mi][ni][0] += f0.x; acc[mi][ni][1] += f0.y;
                acc[mi][ni][2] += f1.x; acc[mi][ni][3] += f1.y;
                acc16[mi][ni][0] = 0u; acc16[mi][ni][1] = 0u;
            }
        if (sn < 32) {
            const int nb = buf ^ 1;
            wps[nb][tid] = wv0;
            if (tid < 64) wps[nb][tid + 256] = wv1;
            *(uint4*)&Bs[nb][br0 * CPITCH + bc16] = bv0;
            *(uint4*)&Bs[nb][(br0 + 32) * CPITCH + bc16] = bv1;
        }
        __syncthreads();
    }

    #pragma unroll
    for (int mi = 0; mi < 4; mi++) {
        int row = i0 + wm + mi * 16 + g;
        #pragma unroll
        for (int ni = 0; ni < 4; ni++) {
            int col = h * HDIM + wn + ni * 8 + 2 * t4;
            size_t o0 = ((size_t)b * SEQ + row) * DIM + col;
            size_t o1 = ((size_t)b * SEQ + row + 8) * DIM + col;
            *(__half2*)&g_ohhi[o0] = __halves2half2(__float2half_rn(acc[mi][ni][0]),
                                                    __float2half_rn(acc[mi][ni][1]));
            *(__half2*)&g_ohhi[o1] = __halves2half2(__float2half_rn(acc[mi][ni][2]),
                                                    __float2half_rn(acc[mi][ni][3]));
        }
    }
}

// ---------------- launch ----------------
extern "C" void kernel_launch(void* const* d_in, const int* in_sizes, int n_in,
                              void* d_out, int out_size) {
    const float* x  = (const float*)d_in[0];
    const float* wq = (const float*)d_in[1];
    const float* wk = (const float*)d_in[2];
    const float* wv = (const float*)d_in[3];
    const float* wp = (const float*)d_in[4];
    const float* bp = (const float*)d_in[5];
    float* out = (float*)d_out;

    void* p2; cudaGetSymbolAddress(&p2, g_xhi);  h16* xhi  = (h16*)p2;
    void* p4; cudaGetSymbolAddress(&p4, g_wvhi); h16* wvhi = (h16*)p4;
    void* p6; cudaGetSymbolAddress(&p6, g_wphi); h16* wphi = (h16*)p6;
    void* p8; cudaGetSymbolAddress(&p8, g_ohhi); h16* ohhi = (h16*)p8;

    const int gemm_smem = 6 * GSTAGE * (int)sizeof(h16);   // 110592
    cudaFuncSetAttribute(gemm_split, cudaFuncAttributeMaxDynamicSharedMemorySize, gemm_smem);

    // 1: x split + partial column sums
    splitx_colsum<<<dim3(DIM / 256, BATCH, 32), 256>>>(x);
    // 2: both weight splits in one launch
    split_w<<<dim3((DIM * DIM) / 1024, 2), 256>>>(wv, wp);
    // 3: xavg
    colsum_final<<<256, 256>>>();
    // 4: v-projection GEMM (profiled launch)
    gemm_split<<<dim3(DIM / 128, MTOT / 128), 256, gemm_smem>>>(
        xhi, wvhi, (const float*)0, (float*)0, 1);

    // attention-weight path
    kavg_kernel<<<(BATCH * DIM * 32) / 256, 256>>>(wk);
    u_kernel<<<dim3(DIM / 256, HEADS, BATCH), 256>>>(wq);
    z_kernel2<<<MTOT / 8, 256>>>();
    softmax_attn2<<<BATCH * HEADS, 256>>>();

    // circular conv (fp16-accum tensor, i-tile 256)
    conv_mma<<<dim3(SEQ / 256, BATCH * HEADS), 256>>>();

    // output projection with bias
    gemm_split<<<dim3(DIM / 128, MTOT / 128), 256, gemm_smem>>>(ohhi, wphi, bp, out, 0);
}

// round 14
// speedup vs baseline: 1.0629x; 1.0629x over previous
#include <cuda_runtime.h>
#include <cuda_fp16.h>
#include <cstdint>

#define BATCH 2
#define SEQ   2048
#define DIM   1024
#define HEADS 16
#define HDIM  64
#define SCALE 0.125f
#define MTOT  4096
#define GPITCH 72
#define CPITCH 72

typedef __half h16;

// ---------------- scratch ----------------
__device__ float g_partial[BATCH * 32 * DIM];
__device__ float g_xavg[BATCH * DIM];
__device__ float g_kavg[BATCH * DIM];
__device__ float g_u[BATCH * HEADS * DIM];
__device__ float g_z[BATCH * HEADS * SEQ];

__device__ h16 g_xhi[(size_t)MTOT * DIM];
__device__ h16 g_wvhi[DIM * DIM];
__device__ h16 g_wphi[DIM * DIM];
__device__ h16 g_vthi[32 * HDIM * SEQ];
__device__ h16 g_a2hi[32 * 4224];
__device__ h16 g_ohhi[(size_t)MTOT * DIM];

// ---------------- PTX helpers ----------------
__device__ __forceinline__ unsigned smem_u32(const void* p) {
    return (unsigned)__cvta_generic_to_shared(p);
}

__device__ __forceinline__ void ldsm_x4(unsigned& r0, unsigned& r1, unsigned& r2, unsigned& r3, unsigned a) {
    asm volatile("ldmatrix.sync.aligned.m8n8.x4.shared.b16 {%0,%1,%2,%3}, [%4];"
                 : "=r"(r0), "=r"(r1), "=r"(r2), "=r"(r3) : "r"(a));
}

__device__ __forceinline__ void mma_f16(float* c, unsigned a0, unsigned a1, unsigned a2, unsigned a3,
                                        unsigned b0, unsigned b1) {
    asm volatile("mma.sync.aligned.m16n8k16.row.col.f32.f16.f16.f32 "
                 "{%0,%1,%2,%3}, {%4,%5,%6,%7}, {%8,%9}, {%0,%1,%2,%3};"
                 : "+f"(c[0]), "+f"(c[1]), "+f"(c[2]), "+f"(c[3])
                 : "r"(a0), "r"(a1), "r"(a2), "r"(a3), "r"(b0), "r"(b1));
}

// ---------------- fused x split + partial column sums ----------------
__global__ void splitx_colsum(const float* __restrict__ x) {
    int c = blockIdx.x * 256 + threadIdx.x;
    int b = blockIdx.y, sz = blockIdx.z;
    const float* xp = x + ((size_t)b * SEQ + (size_t)sz * 64) * DIM + c;
    h16* hp = g_xhi + ((size_t)b * SEQ + (size_t)sz * 64) * DIM + c;
    float sum = 0.f;
    #pragma unroll 8
    for (int n = 0; n < 64; n++) {
        float v = xp[(size_t)n * DIM];
        sum += v;
        hp[(size_t)n * DIM] = __float2half_rn(v);
    }
    g_partial[(b * 32 + sz) * DIM + c] = sum;
}

__global__ void colsum_final() {
    int w = (blockIdx.x * 256 + threadIdx.x) >> 5;
    int lane = threadIdx.x & 31;
    int b = w >> 10, c = w & (DIM - 1);
    float s = g_partial[(b * 32 + lane) * DIM + c];
    #pragma unroll
    for (int o = 16; o > 0; o >>= 1) s += __shfl_xor_sync(0xffffffffu, s, o);
    if (lane == 0) g_xavg[b * DIM + c] = s * (1.0f / SEQ);
}

__global__ void kavg_kernel(const float* __restrict__ wk) {
    int w = (blockIdx.x * blockDim.x + threadIdx.x) >> 5;
    int lane = threadIdx.x & 31;
    int b = w / DIM, co = w % DIM;
    const float* wr = wk + (size_t)co * DIM;
    const float* xa = g_xavg + b * DIM;
    float s = 0.f;
    #pragma unroll 4
    for (int c = lane; c < DIM; c += 32) s += wr[c] * xa[c];
    #pragma unroll
    for (int o = 16; o > 0; o >>= 1) s += __shfl_xor_sync(0xffffffffu, s, o);
    if (lane == 0) g_kavg[b * DIM + co] = s;
}

__global__ void u_kernel(const float* __restrict__ wq) {
    int c = blockIdx.x * 256 + threadIdx.x;
    int h = blockIdx.y, b = blockIdx.z;
    __shared__ float ka[HDIM];
    if (threadIdx.x < HDIM) ka[threadIdx.x] = g_kavg[b * DIM + h * HDIM + threadIdx.x];
    __syncthreads();
    float s = 0.f;
    #pragma unroll
    for (int d = 0; d < HDIM; d++) s += ka[d] * wq[(size_t)(h * HDIM + d) * DIM + c];
    g_u[(b * HEADS + h) * DIM + c] = s;
}

__global__ __launch_bounds__(256) void z_kernel2() {
    __shared__ float us[HEADS][136];
    int tid = threadIdx.x, lane = tid & 31, w = tid >> 5;
    int row = blockIdx.x * 8 + w;
    int b = row >> 11;
    int n = row & (SEQ - 1);
    const __half2* xr = (const __half2*)(g_xhi + (size_t)row * DIM);
    const float* ub = g_u + (size_t)b * HEADS * DIM;

    float acc[HEADS];
    #pragma unroll
    for (int h = 0; h < HEADS; h++) acc[h] = 0.f;

    for (int kc = 0; kc < DIM; kc += 128) {
        for (int t = tid; t < HEADS * 128; t += 256) {
            us[t >> 7][t & 127] = ub[(t >> 7) * DIM + kc + (t & 127)];
        }
        __syncthreads();
        __half2 x01 = xr[(kc >> 1) + lane * 2];
        __half2 x23 = xr[(kc >> 1) + lane * 2 + 1];
        float2 f01 = __half22float2(x01);
        float2 f23 = __half22float2(x23);
        #pragma unroll
        for (int h = 0; h < HEADS; h++) {
            float4 uv = *(const float4*)&us[h][lane * 4];
            acc[h] += f01.x * uv.x + f01.y * uv.y + f23.x * uv.z + f23.y * uv.w;
        }
        __syncthreads();
    }
    #pragma unroll
    for (int h = 0; h < HEADS; h++) {
        float s = acc[h];
        #pragma unroll
        for (int o = 16; o > 0; o >>= 1) s += __shfl_xor_sync(0xffffffffu, s, o);
        if (lane == 0) g_z[((size_t)(b * HEADS + h)) * SEQ + n] = s * SCALE;
    }
}

__global__ void softmax_attn2() {
    int bh = blockIdx.x;
    float* z = g_z + (size_t)bh * SEQ;
    __shared__ float red[256];
    int t = threadIdx.x;
    float m = -1e30f;
    for (int i = t; i < SEQ; i += 256) m = fmaxf(m, z[i]);
    red[t] = m; __syncthreads();
    for (int o = 128; o > 0; o >>= 1) { if (t < o) red[t] = fmaxf(red[t], red[t + o]); __syncthreads(); }
    m = red[0]; __syncthreads();
    float s = 0.f;
    for (int i = t; i < SEQ; i += 256) { float e = __expf(z[i] - m); z[i] = e; s += e; }
    red[t] = s; __syncthreads();
    for (int o = 128; o > 0; o >>= 1) { if (t < o) red[t] += red[t + o]; __syncthreads(); }
    float inv = 1.0f / red[0];
    for (int i = t; i < SEQ; i += 256) z[i] *= inv;
    __syncthreads();
    for (int i = t; i < 4224; i += 256) {
        g_a2hi[bh * 4224 + i] = __float2half_rn(z[i & (SEQ - 1)]);
    }
}

// both weight splits in one launch (blockIdx.y selects)
__global__ void split_w(const float* __restrict__ wv, const float* __restrict__ wp) {
    int i = blockIdx.x * 256 + threadIdx.x;
    const float* in = blockIdx.y ? wp : wv;
    h16* hi = blockIdx.y ? g_wphi : g_wvhi;
    float4 v = ((const float4*)in)[i];
    __half2* H = (__half2*)hi;
    H[i * 2 + 0] = __halves2half2(__float2half_rn(v.x), __float2half_rn(v.y));
    H[i * 2 + 1] = __halves2half2(__float2half_rn(v.z), __float2half_rn(v.w));
}

// ---------------- fp16 tensor GEMM: BK=64, cp.async 3-stage (round-12 form) ----------------
#define GSTAGE (128 * GPITCH)
__global__ __launch_bounds__(256, 2) void gemm_split(
    const h16* __restrict__ Ahi, const h16* __restrict__ Whi,
    const float* __restrict__ bias, float* __restrict__ C, int mode)
{
    extern __shared__ h16 gsm[];
    h16* As_ = gsm;
    h16* Bs_ = gsm + 3 * GSTAGE;
    const int tid = threadIdx.x;
    const int lane = tid & 31;
    const int wid = tid >> 5;
    const int m0 = blockIdx.y * 128;
    const int n0 = blockIdx.x * 128;
    const int wm = (wid >> 2) * 64;
    const int wn = (wid & 3) * 32;
    const int g = lane >> 2;
    const int t4 = lane & 3;

    float acc[4][4][4];
    #pragma unroll
    for (int i = 0; i < 4; i++)
        #pragma unroll
        for (int j = 0; j < 4; j++)
            #pragma unroll
            for (int k = 0; k < 4; k++) acc[i][j][k] = 0.f;

    const int arow = wm + (lane & 15);
    const int acolsel = (lane >> 4) * 8;
    const int bgrp = lane >> 3;
    const int brow = wn + ((bgrp >> 1) * 8) + (lane & 7);
    const int bcolsel = (bgrp & 1) * 8;

    const int lr = tid >> 3;
    const int lc16 = (tid & 7) * 8;

#define G_ISSUE(st_, s_) do {                                                            \
    const int kk_ = (s_) * 64;                                                           \
    _Pragma("unroll")                                                                    \
    for (int rq_ = 0; rq_ < 4; rq_++) {                                                  \
        const int row_ = lr + rq_ * 32;                                                  \
        unsigned sa_ = smem_u32(As_ + (st_) * GSTAGE + row_ * GPITCH + lc16);            \
        const h16* ga_ = Ahi + (size_t)(m0 + row_) * DIM + kk_ + lc16;                   \
        asm volatile("cp.async.cg.shared.global [%0], [%1], 16;" :: "r"(sa_), "l"(ga_)); \
        unsigned sb_ = smem_u32(Bs_ + (st_) * GSTAGE + row_ * GPITCH + lc16);            \
        const h16* gb_ = Whi + (size_t)(n0 + row_) * DIM + kk_ + lc16;                   \
        asm volatile("cp.async.cg.shared.global [%0], [%1], 16;" :: "r"(sb_), "l"(gb_)); \
    }                                                                                    \
    asm volatile("cp.async.commit_group;");                                              \
} while (0)

    G_ISSUE(0, 0);

    for (int s = 0; s < 16; s++) {
        const int st = s % 3;
        if (s + 1 < 16) {
            G_ISSUE((s + 1) % 3, s + 1);
            asm volatile("cp.async.wait_group 1;");
        } else {
            asm volatile("cp.async.wait_group 0;");
        }
        __syncthreads();
        const h16* Ab = As_ + st * GSTAGE;
        const h16* Bb = Bs_ + st * GSTAGE;
        #pragma unroll
        for (int khb = 0; khb < 64; khb += 16) {
            unsigned af[4][4];
            #pragma unroll
            for (int mi = 0; mi < 4; mi++) {
                ldsm_x4(af[mi][0], af[mi][1], af[mi][2], af[mi][3],
                        smem_u32(Ab + (arow + mi * 16) * GPITCH + khb + acolsel));
            }
            unsigned bfr[4][2];
            #pragma unroll
            for (int p = 0; p < 2; p++) {
                unsigned r0, r1, r2, r3;
                ldsm_x4(r0, r1, r2, r3,
                        smem_u32(Bb + (brow + p * 16) * GPITCH + khb + bcolsel));
                bfr[p * 2 + 0][0] = r0; bfr[p * 2 + 0][1] = r1;
                bfr[p * 2 + 1][0] = r2; bfr[p * 2 + 1][1] = r3;
            }
            #pragma unroll
            for (int mi = 0; mi < 4; mi++)
                #pragma unroll
                for (int ni = 0; ni < 4; ni++)
                    mma_f16(acc[mi][ni], af[mi][0], af[mi][1], af[mi][2], af[mi][3],
                            bfr[ni][0], bfr[ni][1]);
        }
    }
#undef G_ISSUE

    if (mode == 0) {
        #pragma unroll
        for (int mi = 0; mi < 4; mi++) {
            int row = m0 + wm + mi * 16 + g;
            #pragma unroll
            for (int ni = 0; ni < 4; ni++) {
                int col = n0 + wn + ni * 8 + 2 * t4;
                float2 bb = *(const float2*)&bias[col];
                float2 v0 = make_float2(acc[mi][ni][0] + bb.x, acc[mi][ni][1] + bb.y);
                float2 v1 = make_float2(acc[mi][ni][2] + bb.x, acc[mi][ni][3] + bb.y);
                *(float2*)&C[(size_t)row * DIM + col] = v0;
                *(float2*)&C[(size_t)(row + 8) * DIM + col] = v1;
            }
        }
    } else {
        #pragma unroll
        for (int mi = 0; mi < 4; mi++) {
            int row = m0 + wm + mi * 16 + g;
            int b = row >> 11;
            int j = row & (SEQ - 1);
            #pragma unroll
            for (int ni = 0; ni < 4; ni++) {
                int col = n0 + wn + ni * 8 + 2 * t4;
                #pragma unroll
                for (int q = 0; q < 4; q++) {
                    int cc = col + (q & 1);
                    int jj = j + (q >> 1) * 8;
                    size_t idx = (((size_t)(b * HEADS + (cc >> 6))) * HDIM + (cc & 63)) * SEQ + jj;
                    g_vthi[idx] = __float2half_rn(acc[mi][ni][q]);
                }
            }
        }
    }
}

// ---------------- fp16 circular conv: i-tile 256, BK=64, cp.async 3-stage B pipeline ----------------
__global__ __launch_bounds__(256) void conv_mma() {
    __shared__ unsigned wps[2][320];
    __shared__ h16 Bs[3][64 * CPITCH];
    const int tid = threadIdx.x;
    const int lane = tid & 31;
    const int wid = tid >> 5;
    const int i0 = blockIdx.x * 256;
    const int bh = blockIdx.y;
    const int b = bh >> 4;
    const int h = bh & 15;
    const int wm = (wid >> 1) * 64;
    const int wn = (wid & 1) * 32;
    const int g = lane >> 2;
    const int t4 = lane & 3;

    const unsigned short* a2h = (const unsigned short*)(g_a2hi + (size_t)bh * 4224);
    const h16* vth = g_vthi + (size_t)bh * HDIM * SEQ;

    float acc[4][4][4];
    #pragma unroll
    for (int i = 0; i < 4; i++)
        #pragma unroll
        for (int j = 0; j < 4; j++)
            #pragma unroll
            for (int k = 0; k < 4; k++) acc[i][j][k] = 0.f;

    const int br0 = tid >> 3;
    const int bc16 = (tid & 7) * 8;
    const int bgrp = lane >> 3;
    const int brow = wn + ((bgrp >> 1) * 8) + (lane & 7);
    const int bcolsel = (bgrp & 1) * 8;

#define C_ISSUE(st_, s_) do {                                                            \
    const int j0_ = (s_) * 64;                                                           \
    unsigned sb0_ = smem_u32(&Bs[st_][br0 * CPITCH + bc16]);                             \
    const h16* gb0_ = vth + (size_t)br0 * SEQ + j0_ + bc16;                              \
    asm volatile("cp.async.cg.shared.global [%0], [%1], 16;" :: "r"(sb0_), "l"(gb0_));   \
    unsigned sb1_ = smem_u32(&Bs[st_][(br0 + 32) * CPITCH + bc16]);                      \
    const h16* gb1_ = vth + (size_t)(br0 + 32) * SEQ + j0_ + bc16;                       \
    asm volatile("cp.async.cg.shared.global [%0], [%1], 16;" :: "r"(sb1_), "l"(gb1_));   \
    asm volatile("cp.async.commit_group;");                                              \
} while (0)

    // prologue: attn window 0 + B stage 0
    {
        const int ws = 1793 - i0;
        wps[0][tid] = (unsigned)a2h[ws + tid] | ((unsigned)a2h[ws + tid + 1] << 16);
        if (tid < 64) {
            int t2 = tid + 256;
            wps[0][t2] = (unsigned)a2h[ws + t2] | ((unsigned)a2h[ws + t2 + 1] << 16);
        }
    }
    C_ISSUE(0, 0);

    for (int s = 0; s < 32; s++) {
        const int st = s % 3;
        const int buf = s & 1;
        const int sn = s + 1;
        // prefetch next attn window into regs
        unsigned wv0 = 0u, wv1 = 0u;
        if (sn < 32) {
            const int ws = 1793 + sn * 64 - i0;
            wv0 = (unsigned)a2h[ws + tid] | ((unsigned)a2h[ws + tid + 1] << 16);
            if (tid < 64) {
                int t2 = tid + 256;
                wv1 = (unsigned)a2h[ws + t2] | ((unsigned)a2h[ws + t2 + 1] << 16);
            }
        }
        if (sn < 32) {
            C_ISSUE(sn % 3, sn);
            asm volatile("cp.async.wait_group 1;");
        } else {
            asm volatile("cp.async.wait_group 0;");
        }
        __syncthreads();
        #pragma unroll
        for (int khb = 0; khb < 64; khb += 16) {
            const int ub = 255 - (wm + g) + 2 * t4 + khb;
            unsigned fa0[4], fa1[4], fa2[4];
            #pragma unroll
            for (int mi = 0; mi < 4; mi++) {
                const int u = ub - mi * 16;
                fa0[mi] = wps[buf][u];
                fa1[mi] = wps[buf][u - 8];
                fa2[mi] = wps[buf][u + 8];
            }
            unsigned bfr[4][2];
            #pragma unroll
            for (int p = 0; p < 2; p++) {
                unsigned r0, r1, r2, r3;
                ldsm_x4(r0, r1, r2, r3,
                        smem_u32(&Bs[st][(brow + p * 16) * CPITCH + khb + bcolsel]));
                bfr[p * 2 + 0][0] = r0; bfr[p * 2 + 0][1] = r1;
                bfr[p * 2 + 1][0] = r2; bfr[p * 2 + 1][1] = r3;
            }
            #pragma unroll
            for (int mi = 0; mi < 4; mi++)
                #pragma unroll
                for (int ni = 0; ni < 4; ni++)
                    mma_f16(acc[mi][ni], fa0[mi], fa1[mi], fa2[mi], fa0[mi],
                            bfr[ni][0], bfr[ni][1]);
        }
        if (sn < 32) {
            const int nb = buf ^ 1;
            wps[nb][tid] = wv0;
            if (tid < 64) wps[nb][tid + 256] = wv1;
        }
    }
#undef C_ISSUE

    #pragma unroll
    for (int mi = 0; mi < 4; mi++) {
        int row = i0 + wm + mi * 16 + g;
        #pragma unroll
        for (int ni = 0; ni < 4; ni++) {
            int col = h * HDIM + wn + ni * 8 + 2 * t4;
            size_t o0 = ((size_t)b * SEQ + row) * DIM + col;
            size_t o1 = ((size_t)b * SEQ + row + 8) * DIM + col;
            *(__half2*)&g_ohhi[o0] = __halves2half2(__float2half_rn(acc[mi][ni][0]),
                                                    __float2half_rn(acc[mi][ni][1]));
            *(__half2*)&g_ohhi[o1] = __halves2half2(__float2half_rn(acc[mi][ni][2]),
                                                    __float2half_rn(acc[mi][ni][3]));
        }
    }
}

// ---------------- launch ----------------
extern "C" void kernel_launch(void* const* d_in, const int* in_sizes, int n_in,
                              void* d_out, int out_size) {
    const float* x  = (const float*)d_in[0];
    const float* wq = (const float*)d_in[1];
    const float* wk = (const float*)d_in[2];
    const float* wv = (const float*)d_in[3];
    const float* wp = (const float*)d_in[4];
    const float* bp = (const float*)d_in[5];
    float* out = (float*)d_out;

    void* p2; cudaGetSymbolAddress(&p2, g_xhi);  h16* xhi  = (h16*)p2;
    void* p4; cudaGetSymbolAddress(&p4, g_wvhi); h16* wvhi = (h16*)p4;
    void* p6; cudaGetSymbolAddress(&p6, g_wphi); h16* wphi = (h16*)p6;
    void* p8; cudaGetSymbolAddress(&p8, g_ohhi); h16* ohhi = (h16*)p8;

    const int gemm_smem = 6 * GSTAGE * (int)sizeof(h16);   // 110592
    cudaFuncSetAttribute(gemm_split, cudaFuncAttributeMaxDynamicSharedMemorySize, gemm_smem);

    // 1: x split + partial column sums
    splitx_colsum<<<dim3(DIM / 256, BATCH, 32), 256>>>(x);
    // 2: both weight splits in one launch
    split_w<<<dim3((DIM * DIM) / 1024, 2), 256>>>(wv, wp);
    // 3: xavg
    colsum_final<<<256, 256>>>();
    // 4: v-projection GEMM
    gemm_split<<<dim3(DIM / 128, MTOT / 128), 256, gemm_smem>>>(
        xhi, wvhi, (const float*)0, (float*)0, 1);

    // attention-weight path
    kavg_kernel<<<(BATCH * DIM * 32) / 256, 256>>>(wk);
    u_kernel<<<dim3(DIM / 256, HEADS, BATCH), 256>>>(wq);
    z_kernel2<<<MTOT / 8, 256>>>();
    softmax_attn2<<<BATCH * HEADS, 256>>>();

    // circular conv (cp.async pipeline, i-tile 256)
    conv_mma<<<dim3(SEQ / 256, BATCH * HEADS), 256>>>();

    // output projection with bias
    gemm_split<<<dim3(DIM / 128, MTOT / 128), 256, gemm_smem>>>(ohhi, wphi, bp, out, 0);
}

// round 15
// speedup vs baseline: 1.1580x; 1.0895x over previous
#include <cuda_runtime.h>
#include <cuda_fp16.h>
#include <cstdint>

#define BATCH 2
#define SEQ   2048
#define DIM   1024
#define HEADS 16
#define HDIM  64
#define SCALE 0.125f
#define MTOT  4096
#define GPITCH 72
#define CPITCH 72

typedef __half h16;

// ---------------- scratch ----------------
__device__ float g_partial[BATCH * 32 * DIM];
__device__ float g_xavg[BATCH * DIM];
__device__ float g_kavg[BATCH * DIM];
__device__ float g_u[BATCH * HEADS * DIM];
__device__ float g_z[BATCH * HEADS * SEQ];

__device__ h16 g_xhi[(size_t)MTOT * DIM];
__device__ h16 g_wvhi[DIM * DIM];
__device__ h16 g_wphi[DIM * DIM];
__device__ h16 g_vthi[32 * HDIM * SEQ];
__device__ h16 g_a2hi[32 * 4224];
__device__ h16 g_ohhi[(size_t)MTOT * DIM];

// ---------------- PTX helpers ----------------
__device__ __forceinline__ unsigned smem_u32(const void* p) {
    return (unsigned)__cvta_generic_to_shared(p);
}

__device__ __forceinline__ void ldsm_x4(unsigned& r0, unsigned& r1, unsigned& r2, unsigned& r3, unsigned a) {
    asm volatile("ldmatrix.sync.aligned.m8n8.x4.shared.b16 {%0,%1,%2,%3}, [%4];"
                 : "=r"(r0), "=r"(r1), "=r"(r2), "=r"(r3) : "r"(a));
}

__device__ __forceinline__ void mma_f16(float* c, unsigned a0, unsigned a1, unsigned a2, unsigned a3,
                                        unsigned b0, unsigned b1) {
    asm volatile("mma.sync.aligned.m16n8k16.row.col.f32.f16.f16.f32 "
                 "{%0,%1,%2,%3}, {%4,%5,%6,%7}, {%8,%9}, {%0,%1,%2,%3};"
                 : "+f"(c[0]), "+f"(c[1]), "+f"(c[2]), "+f"(c[3])
                 : "r"(a0), "r"(a1), "r"(a2), "r"(a3), "r"(b0), "r"(b1));
}

// ---------------- fused x split + partial column sums ----------------
__global__ void splitx_colsum(const float* __restrict__ x) {
    int c = blockIdx.x * 256 + threadIdx.x;
    int b = blockIdx.y, sz = blockIdx.z;
    const float* xp = x + ((size_t)b * SEQ + (size_t)sz * 64) * DIM + c;
    h16* hp = g_xhi + ((size_t)b * SEQ + (size_t)sz * 64) * DIM + c;
    float sum = 0.f;
    #pragma unroll 8
    for (int n = 0; n < 64; n++) {
        float v = xp[(size_t)n * DIM];
        sum += v;
        hp[(size_t)n * DIM] = __float2half_rn(v);
    }
    g_partial[(b * 32 + sz) * DIM + c] = sum;
}

// fused: weight splits (blocks 0..2047) + xavg final reduce (blocks 2048..2303)
__global__ void splitw_xavg(const float* __restrict__ wv, const float* __restrict__ wp) {
    int bx = blockIdx.x;
    int tid = threadIdx.x;
    if (bx < 2048) {
        int i = (bx & 1023) * 256 + tid;
        const float* in = (bx >= 1024) ? wp : wv;
        h16* hi = (bx >= 1024) ? g_wphi : g_wvhi;
        float4 v = ((const float4*)in)[i];
        __half2* H = (__half2*)hi;
        H[i * 2 + 0] = __halves2half2(__float2half_rn(v.x), __float2half_rn(v.y));
        H[i * 2 + 1] = __halves2half2(__float2half_rn(v.z), __float2half_rn(v.w));
    } else {
        int w = ((bx - 2048) * 256 + tid) >> 5;   // 0..2047
        int lane = tid & 31;
        int b = w >> 10, c = w & (DIM - 1);
        float s = g_partial[(b * 32 + lane) * DIM + c];
        #pragma unroll
        for (int o = 16; o > 0; o >>= 1) s += __shfl_xor_sync(0xffffffffu, s, o);
        if (lane == 0) g_xavg[b * DIM + c] = s * (1.0f / SEQ);
    }
}

__global__ void kavg_kernel(const float* __restrict__ wk) {
    int w = (blockIdx.x * blockDim.x + threadIdx.x) >> 5;
    int lane = threadIdx.x & 31;
    int b = w / DIM, co = w % DIM;
    const float* wr = wk + (size_t)co * DIM;
    const float* xa = g_xavg + b * DIM;
    float s = 0.f;
    #pragma unroll 4
    for (int c = lane; c < DIM; c += 32) s += wr[c] * xa[c];
    #pragma unroll
    for (int o = 16; o > 0; o >>= 1) s += __shfl_xor_sync(0xffffffffu, s, o);
    if (lane == 0) g_kavg[b * DIM + co] = s;
}

__global__ void u_kernel(const float* __restrict__ wq) {
    int c = blockIdx.x * 256 + threadIdx.x;
    int h = blockIdx.y, b = blockIdx.z;
    __shared__ float ka[HDIM];
    if (threadIdx.x < HDIM) ka[threadIdx.x] = g_kavg[b * DIM + h * HDIM + threadIdx.x];
    __syncthreads();
    float s = 0.f;
    #pragma unroll
    for (int d = 0; d < HDIM; d++) s += ka[d] * wq[(size_t)(h * HDIM + d) * DIM + c];
    g_u[(b * HEADS + h) * DIM + c] = s;
}

// z: 32 rows per block (4 rows per warp) — cuts u re-staging traffic 4x
__global__ __launch_bounds__(256) void z_kernel3() {
    __shared__ float us[HEADS][132];
    int tid = threadIdx.x, lane = tid & 31, w = tid >> 5;
    int row0 = blockIdx.x * 32 + w * 4;
    int b = row0 >> 11;
    const float* ub = g_u + (size_t)b * HEADS * DIM;

    float acc[4][HEADS];
    #pragma unroll
    for (int r = 0; r < 4; r++)
        #pragma unroll
        for (int h = 0; h < HEADS; h++) acc[r][h] = 0.f;

    for (int kc = 0; kc < DIM; kc += 128) {
        for (int t = tid; t < HEADS * 128; t += 256) {
            us[t >> 7][t & 127] = ub[(t >> 7) * DIM + kc + (t & 127)];
        }
        __syncthreads();
        #pragma unroll
        for (int r = 0; r < 4; r++) {
            const __half2* xr = (const __half2*)(g_xhi + (size_t)(row0 + r) * DIM);
            __half2 x01 = xr[(kc >> 1) + lane * 2];
            __half2 x23 = xr[(kc >> 1) + lane * 2 + 1];
            float2 f01 = __half22float2(x01);
            float2 f23 = __half22float2(x23);
            #pragma unroll
            for (int h = 0; h < HEADS; h++) {
                float4 uv = *(const float4*)&us[h][lane * 4];
                acc[r][h] += f01.x * uv.x + f01.y * uv.y + f23.x * uv.z + f23.y * uv.w;
            }
        }
        __syncthreads();
    }
    #pragma unroll
    for (int r = 0; r < 4; r++) {
        int n = (row0 + r) & (SEQ - 1);
        #pragma unroll
        for (int h = 0; h < HEADS; h++) {
            float s = acc[r][h];
            #pragma unroll
            for (int o = 16; o > 0; o >>= 1) s += __shfl_xor_sync(0xffffffffu, s, o);
            if (lane == 0) g_z[((size_t)(b * HEADS + h)) * SEQ + n] = s * SCALE;
        }
    }
}

__global__ void softmax_attn2() {
    int bh = blockIdx.x;
    float* z = g_z + (size_t)bh * SEQ;
    __shared__ float red[256];
    int t = threadIdx.x;
    float m = -1e30f;
    for (int i = t; i < SEQ; i += 256) m = fmaxf(m, z[i]);
    red[t] = m; __syncthreads();
    for (int o = 128; o > 0; o >>= 1) { if (t < o) red[t] = fmaxf(red[t], red[t + o]); __syncthreads(); }
    m = red[0]; __syncthreads();
    float s = 0.f;
    for (int i = t; i < SEQ; i += 256) { float e = __expf(z[i] - m); z[i] = e; s += e; }
    red[t] = s; __syncthreads();
    for (int o = 128; o > 0; o >>= 1) { if (t < o) red[t] += red[t + o]; __syncthreads(); }
    float inv = 1.0f / red[0];
    for (int i = t; i < SEQ; i += 256) z[i] *= inv;
    __syncthreads();
    for (int i = t; i < 4224; i += 256) {
        g_a2hi[bh * 4224 + i] = __float2half_rn(z[i & (SEQ - 1)]);
    }
}

// ---------------- fp16 tensor GEMM: BK=64, cp.async 3-stage (round-12 form) ----------------
#define GSTAGE (128 * GPITCH)
__global__ __launch_bounds__(256, 2) void gemm_split(
    const h16* __restrict__ Ahi, const h16* __restrict__ Whi,
    const float* __restrict__ bias, float* __restrict__ C, int mode)
{
    extern __shared__ h16 gsm[];
    h16* As_ = gsm;
    h16* Bs_ = gsm + 3 * GSTAGE;
    const int tid = threadIdx.x;
    const int lane = tid & 31;
    const int wid = tid >> 5;
    const int m0 = blockIdx.y * 128;
    const int n0 = blockIdx.x * 128;
    const int wm = (wid >> 2) * 64;
    const int wn = (wid & 3) * 32;
    const int g = lane >> 2;
    const int t4 = lane & 3;

    float acc[4][4][4];
    #pragma unroll
    for (int i = 0; i < 4; i++)
        #pragma unroll
        for (int j = 0; j < 4; j++)
            #pragma unroll
            for (int k = 0; k < 4; k++) acc[i][j][k] = 0.f;

    const int arow = wm + (lane & 15);
    const int acolsel = (lane >> 4) * 8;
    const int bgrp = lane >> 3;
    const int brow = wn + ((bgrp >> 1) * 8) + (lane & 7);
    const int bcolsel = (bgrp & 1) * 8;

    const int lr = tid >> 3;
    const int lc16 = (tid & 7) * 8;

#define G_ISSUE(st_, s_) do {                                                            \
    const int kk_ = (s_) * 64;                                                           \
    _Pragma("unroll")                                                                    \
    for (int rq_ = 0; rq_ < 4; rq_++) {                                                  \
        const int row_ = lr + rq_ * 32;                                                  \
        unsigned sa_ = smem_u32(As_ + (st_) * GSTAGE + row_ * GPITCH + lc16);            \
        const h16* ga_ = Ahi + (size_t)(m0 + row_) * DIM + kk_ + lc16;                   \
        asm volatile("cp.async.cg.shared.global [%0], [%1], 16;" :: "r"(sa_), "l"(ga_)); \
        unsigned sb_ = smem_u32(Bs_ + (st_) * GSTAGE + row_ * GPITCH + lc16);            \
        const h16* gb_ = Whi + (size_t)(n0 + row_) * DIM + kk_ + lc16;                   \
        asm volatile("cp.async.cg.shared.global [%0], [%1], 16;" :: "r"(sb_), "l"(gb_)); \
    }                                                                                    \
    asm volatile("cp.async.commit_group;");                                              \
} while (0)

    G_ISSUE(0, 0);

    for (int s = 0; s < 16; s++) {
        const int st = s % 3;
        if (s + 1 < 16) {
            G_ISSUE((s + 1) % 3, s + 1);
            asm volatile("cp.async.wait_group 1;");
        } else {
            asm volatile("cp.async.wait_group 0;");
        }
        __syncthreads();
        const h16* Ab = As_ + st * GSTAGE;
        const h16* Bb = Bs_ + st * GSTAGE;
        #pragma unroll
        for (int khb = 0; khb < 64; khb += 16) {
            unsigned af[4][4];
            #pragma unroll
            for (int mi = 0; mi < 4; mi++) {
                ldsm_x4(af[mi][0], af[mi][1], af[mi][2], af[mi][3],
                        smem_u32(Ab + (arow + mi * 16) * GPITCH + khb + acolsel));
            }
            unsigned bfr[4][2];
            #pragma unroll
            for (int p = 0; p < 2; p++) {
                unsigned r0, r1, r2, r3;
                ldsm_x4(r0, r1, r2, r3,
                        smem_u32(Bb + (brow + p * 16) * GPITCH + khb + bcolsel));
                bfr[p * 2 + 0][0] = r0; bfr[p * 2 + 0][1] = r1;
                bfr[p * 2 + 1][0] = r2; bfr[p * 2 + 1][1] = r3;
            }
            #pragma unroll
            for (int mi = 0; mi < 4; mi++)
                #pragma unroll
                for (int ni = 0; ni < 4; ni++)
                    mma_f16(acc[mi][ni], af[mi][0], af[mi][1], af[mi][2], af[mi][3],
                            bfr[ni][0], bfr[ni][1]);
        }
    }
#undef G_ISSUE

    if (mode == 0) {
        #pragma unroll
        for (int mi = 0; mi < 4; mi++) {
            int row = m0 + wm + mi * 16 + g;
            #pragma unroll
            for (int ni = 0; ni < 4; ni++) {
                int col = n0 + wn + ni * 8 + 2 * t4;
                float2 bb = *(const float2*)&bias[col];
                float2 v0 = make_float2(acc[mi][ni][0] + bb.x, acc[mi][ni][1] + bb.y);
                float2 v1 = make_float2(acc[mi][ni][2] + bb.x, acc[mi][ni][3] + bb.y);
                *(float2*)&C[(size_t)row * DIM + col] = v0;
                *(float2*)&C[(size_t)(row + 8) * DIM + col] = v1;
            }
        }
    } else {
        #pragma unroll
        for (int mi = 0; mi < 4; mi++) {
            int row = m0 + wm + mi * 16 + g;
            int b = row >> 11;
            int j = row & (SEQ - 1);
            #pragma unroll
            for (int ni = 0; ni < 4; ni++) {
                int col = n0 + wn + ni * 8 + 2 * t4;
                #pragma unroll
                for (int q = 0; q < 4; q++) {
                    int cc = col + (q & 1);
                    int jj = j + (q >> 1) * 8;
                    size_t idx = (((size_t)(b * HEADS + (cc >> 6))) * HDIM + (cc & 63)) * SEQ + jj;
                    g_vthi[idx] = __float2half_rn(acc[mi][ni][q]);
                }
            }
        }
    }
}

// ---------------- fp16 circular conv, i-tile 256, BK=64 (round-12 exact) ----------------
__global__ __launch_bounds__(256) void conv_mma() {
    __shared__ unsigned wps[2][320];
    __shared__ h16 Bs[2][64 * CPITCH];
    const int tid = threadIdx.x;
    const int lane = tid & 31;
    const int wid = tid >> 5;
    const int i0 = blockIdx.x * 256;
    const int bh = blockIdx.y;
    const int b = bh >> 4;
    const int h = bh & 15;
    const int wm = (wid >> 1) * 64;
    const int wn = (wid & 1) * 32;
    const int g = lane >> 2;
    const int t4 = lane & 3;

    const unsigned short* a2h = (const unsigned short*)(g_a2hi + (size_t)bh * 4224);
    const h16* vth = g_vthi + (size_t)bh * HDIM * SEQ;

    float acc[4][4][4];
    #pragma unroll
    for (int i = 0; i < 4; i++)
        #pragma unroll
        for (int j = 0; j < 4; j++)
            #pragma unroll
            for (int k = 0; k < 4; k++) acc[i][j][k] = 0.f;

    const int br0 = tid >> 3;
    const int bc16 = (tid & 7) * 8;
    const int bgrp = lane >> 3;
    const int brow = wn + ((bgrp >> 1) * 8) + (lane & 7);
    const int bcolsel = (bgrp & 1) * 8;

    {
        const int ws = 1793 - i0;
        wps[0][tid] = (unsigned)a2h[ws + tid] | ((unsigned)a2h[ws + tid + 1] << 16);
        if (tid < 64) {
            int t2 = tid + 256;
            wps[0][t2] = (unsigned)a2h[ws + t2] | ((unsigned)a2h[ws + t2 + 1] << 16);
        }
        uint4 pb0 = *(const uint4*)(vth + (size_t)br0 * SEQ + bc16);
        uint4 pb1 = *(const uint4*)(vth + (size_t)(br0 + 32) * SEQ + bc16);
        *(uint4*)&Bs[0][br0 * CPITCH + bc16] = pb0;
        *(uint4*)&Bs[0][(br0 + 32) * CPITCH + bc16] = pb1;
    }
    __syncthreads();

    for (int s = 0; s < 32; s++) {
        const int buf = s & 1;
        const int sn = s + 1;
        unsigned wv0 = 0u, wv1 = 0u;
        uint4 bv0, bv1;
        if (sn < 32) {
            const int j0 = sn * 64;
            const int ws = 1793 + j0 - i0;
            wv0 = (unsigned)a2h[ws + tid] | ((unsigned)a2h[ws + tid + 1] << 16);
            if (tid < 64) {
                int t2 = tid + 256;
                wv1 = (unsigned)a2h[ws + t2] | ((unsigned)a2h[ws + t2 + 1] << 16);
            }
            bv0 = *(const uint4*)(vth + (size_t)br0 * SEQ + j0 + bc16);
            bv1 = *(const uint4*)(vth + (size_t)(br0 + 32) * SEQ + j0 + bc16);
        }
        #pragma unroll
        for (int khb = 0; khb < 64; khb += 16) {
            const int ub = 255 - (wm + g) + 2 * t4 + khb;
            unsigned fa0[4], fa1[4], fa2[4];
            #pragma unroll
            for (int mi = 0; mi < 4; mi++) {
                const int u = ub - mi * 16;
                fa0[mi] = wps[buf][u];
                fa1[mi] = wps[buf][u - 8];
                fa2[mi] = wps[buf][u + 8];
            }
            unsigned bfr[4][2];
            #pragma unroll
            for (int p = 0; p < 2; p++) {
                unsigned r0, r1, r2, r3;
                ldsm_x4(r0, r1, r2, r3,
                        smem_u32(&Bs[buf][(brow + p * 16) * CPITCH + khb + bcolsel]));
                bfr[p * 2 + 0][0] = r0; bfr[p * 2 + 0][1] = r1;
                bfr[p * 2 + 1][0] = r2; bfr[p * 2 + 1][1] = r3;
            }
            #pragma unroll
            for (int mi = 0; mi < 4; mi++)
                #pragma unroll
                for (int ni = 0; ni < 4; ni++)
                    mma_f16(acc[mi][ni], fa0[mi], fa1[mi], fa2[mi], fa0[mi],
                            bfr[ni][0], bfr[ni][1]);
        }
        if (sn < 32) {
            const int nb = buf ^ 1;
            wps[nb][tid] = wv0;
            if (tid < 64) wps[nb][tid + 256] = wv1;
            *(uint4*)&Bs[nb][br0 * CPITCH + bc16] = bv0;
            *(uint4*)&Bs[nb][(br0 + 32) * CPITCH + bc16] = bv1;
        }
        __syncthreads();
    }

    #pragma unroll
    for (int mi = 0; mi < 4; mi++) {
        int row = i0 + wm + mi * 16 + g;
        #pragma unroll
        for (int ni = 0; ni < 4; ni++) {
            int col = h * HDIM + wn + ni * 8 + 2 * t4;
            size_t o0 = ((size_t)b * SEQ + row) * DIM + col;
            size_t o1 = ((size_t)b * SEQ + row + 8) * DIM + col;
            *(__half2*)&g_ohhi[o0] = __halves2half2(__float2half_rn(acc[mi][ni][0]),
                                                    __float2half_rn(acc[mi][ni][1]));
            *(__half2*)&g_ohhi[o1] = __halves2half2(__float2half_rn(acc[mi][ni][2]),
                                                    __float2half_rn(acc[mi][ni][3]));
        }
    }
}

// ---------------- launch ----------------
extern "C" void kernel_launch(void* const* d_in, const int* in_sizes, int n_in,
                              void* d_out, int out_size) {
    const float* x  = (const float*)d_in[0];
    const float* wq = (const float*)d_in[1];
    const float* wk = (const float*)d_in[2];
    const float* wv = (const float*)d_in[3];
    const float* wp = (const float*)d_in[4];
    const float* bp = (const float*)d_in[5];
    float* out = (float*)d_out;

    void* p2; cudaGetSymbolAddress(&p2, g_xhi);  h16* xhi  = (h16*)p2;
    void* p4; cudaGetSymbolAddress(&p4, g_wvhi); h16* wvhi = (h16*)p4;
    void* p6; cudaGetSymbolAddress(&p6, g_wphi); h16* wphi = (h16*)p6;
    void* p8; cudaGetSymbolAddress(&p8, g_ohhi); h16* ohhi = (h16*)p8;

    const int gemm_smem = 6 * GSTAGE * (int)sizeof(h16);   // 110592
    cudaFuncSetAttribute(gemm_split, cudaFuncAttributeMaxDynamicSharedMemorySize, gemm_smem);

    // 1: x split + partial column sums
    splitx_colsum<<<dim3(DIM / 256, BATCH, 32), 256>>>(x);
    // 2: weight splits + xavg final reduce (fused independent work)
    splitw_xavg<<<2304, 256>>>(wv, wp);
    // 3: v-projection GEMM
    gemm_split<<<dim3(DIM / 128, MTOT / 128), 256, gemm_smem>>>(
        xhi, wvhi, (const float*)0, (float*)0, 1);

    // attention-weight path
    kavg_kernel<<<(BATCH * DIM * 32) / 256, 256>>>(wk);
    u_kernel<<<dim3(DIM / 256, HEADS, BATCH), 256>>>(wq);
    z_kernel3<<<MTOT / 32, 256>>>();
    softmax_attn2<<<BATCH * HEADS, 256>>>();

    // circular conv (round-12 register double-buffer, i-tile 256)
    conv_mma<<<dim3(SEQ / 256, BATCH * HEADS), 256>>>();

    // output projection with bias
    gemm_split<<<dim3(DIM / 128, MTOT / 128), 256, gemm_smem>>>(ohhi, wphi, bp, out, 0);
}

// round 16
// speedup vs baseline: 1.1657x; 1.0067x over previous
#include <cuda_runtime.h>
#include <cuda_fp16.h>
#include <cstdint>

#define BATCH 2
#define SEQ   2048
#define DIM   1024
#define HEADS 16
#define HDIM  64
#define SCALE 0.125f
#define MTOT  4096
#define GPITCH 72
#define CPITCH 72

typedef __half h16;

// ---------------- scratch ----------------
__device__ float g_partial[BATCH * 32 * DIM];
__device__ float g_xavg[BATCH * DIM];
__device__ float g_kavg[BATCH * DIM];
__device__ float g_u[BATCH * HEADS * DIM];
__device__ float g_z[BATCH * HEADS * SEQ];

__device__ h16 g_xhi[(size_t)MTOT * DIM];
__device__ h16 g_wvhi[DIM * DIM];
__device__ h16 g_wphi[DIM * DIM];
__device__ h16 g_vthi[32 * HDIM * SEQ];
__device__ h16 g_a2hi[32 * 4224];
__device__ h16 g_ohhi[(size_t)MTOT * DIM];

// ---------------- PTX helpers ----------------
__device__ __forceinline__ unsigned smem_u32(const void* p) {
    return (unsigned)__cvta_generic_to_shared(p);
}

__device__ __forceinline__ void ldsm_x4(unsigned& r0, unsigned& r1, unsigned& r2, unsigned& r3, unsigned a) {
    asm volatile("ldmatrix.sync.aligned.m8n8.x4.shared.b16 {%0,%1,%2,%3}, [%4];"
                 : "=r"(r0), "=r"(r1), "=r"(r2), "=r"(r3) : "r"(a));
}

__device__ __forceinline__ void mma_f16(float* c, unsigned a0, unsigned a1, unsigned a2, unsigned a3,
                                        unsigned b0, unsigned b1) {
    asm volatile("mma.sync.aligned.m16n8k16.row.col.f32.f16.f16.f32 "
                 "{%0,%1,%2,%3}, {%4,%5,%6,%7}, {%8,%9}, {%0,%1,%2,%3};"
                 : "+f"(c[0]), "+f"(c[1]), "+f"(c[2]), "+f"(c[3])
                 : "r"(a0), "r"(a1), "r"(a2), "r"(a3), "r"(b0), "r"(b1));
}

// ---------------- fused x split + partial column sums ----------------
__global__ void splitx_colsum(const float* __restrict__ x) {
    int c = blockIdx.x * 256 + threadIdx.x;
    int b = blockIdx.y, sz = blockIdx.z;
    const float* xp = x + ((size_t)b * SEQ + (size_t)sz * 64) * DIM + c;
    h16* hp = g_xhi + ((size_t)b * SEQ + (size_t)sz * 64) * DIM + c;
    float sum = 0.f;
    #pragma unroll 8
    for (int n = 0; n < 64; n++) {
        float v = xp[(size_t)n * DIM];
        sum += v;
        hp[(size_t)n * DIM] = __float2half_rn(v);
    }
    g_partial[(b * 32 + sz) * DIM + c] = sum;
}

// fused: weight splits (blocks 0..2047) + xavg final reduce (blocks 2048..2303)
__global__ void splitw_xavg(const float* __restrict__ wv, const float* __restrict__ wp) {
    int bx = blockIdx.x;
    int tid = threadIdx.x;
    if (bx < 2048) {
        int i = (bx & 1023) * 256 + tid;
        const float* in = (bx >= 1024) ? wp : wv;
        h16* hi = (bx >= 1024) ? g_wphi : g_wvhi;
        float4 v = ((const float4*)in)[i];
        __half2* H = (__half2*)hi;
        H[i * 2 + 0] = __halves2half2(__float2half_rn(v.x), __float2half_rn(v.y));
        H[i * 2 + 1] = __halves2half2(__float2half_rn(v.z), __float2half_rn(v.w));
    } else {
        int w = ((bx - 2048) * 256 + tid) >> 5;   // 0..2047
        int lane = tid & 31;
        int b = w >> 10, c = w & (DIM - 1);
        float s = g_partial[(b * 32 + lane) * DIM + c];
        #pragma unroll
        for (int o = 16; o > 0; o >>= 1) s += __shfl_xor_sync(0xffffffffu, s, o);
        if (lane == 0) g_xavg[b * DIM + c] = s * (1.0f / SEQ);
    }
}

// kavg for BOTH batches per warp: wk row read once
__global__ void kavg2_kernel(const float* __restrict__ wk) {
    int co = (blockIdx.x * blockDim.x + threadIdx.x) >> 5;   // 0..1023
    int lane = threadIdx.x & 31;
    const float* wr = wk + (size_t)co * DIM;
    float s0 = 0.f, s1 = 0.f;
    #pragma unroll 4
    for (int c = lane; c < DIM; c += 32) {
        float w = wr[c];
        s0 += w * g_xavg[c];
        s1 += w * g_xavg[DIM + c];
    }
    #pragma unroll
    for (int o = 16; o > 0; o >>= 1) {
        s0 += __shfl_xor_sync(0xffffffffu, s0, o);
        s1 += __shfl_xor_sync(0xffffffffu, s1, o);
    }
    if (lane == 0) {
        g_kavg[co] = s0;
        g_kavg[DIM + co] = s1;
    }
}

// u for BOTH batches per block: wq rows read once
__global__ void u2_kernel(const float* __restrict__ wq) {
    int c = blockIdx.x * 256 + threadIdx.x;
    int h = blockIdx.y;
    __shared__ float ka[2][HDIM];
    if (threadIdx.x < 2 * HDIM)
        ka[threadIdx.x >> 6][threadIdx.x & 63] =
            g_kavg[(threadIdx.x >> 6) * DIM + h * HDIM + (threadIdx.x & 63)];
    __syncthreads();
    float s0 = 0.f, s1 = 0.f;
    #pragma unroll
    for (int d = 0; d < HDIM; d++) {
        float w = wq[(size_t)(h * HDIM + d) * DIM + c];
        s0 += ka[0][d] * w;
        s1 += ka[1][d] * w;
    }
    g_u[(size_t)h * DIM + c] = s0;
    g_u[((size_t)HEADS + h) * DIM + c] = s1;
}

// z: 32 rows per block (4 rows per warp)
__global__ __launch_bounds__(256) void z_kernel3() {
    __shared__ float us[HEADS][132];
    int tid = threadIdx.x, lane = tid & 31, w = tid >> 5;
    int row0 = blockIdx.x * 32 + w * 4;
    int b = row0 >> 11;
    const float* ub = g_u + (size_t)b * HEADS * DIM;

    float acc[4][HEADS];
    #pragma unroll
    for (int r = 0; r < 4; r++)
        #pragma unroll
        for (int h = 0; h < HEADS; h++) acc[r][h] = 0.f;

    for (int kc = 0; kc < DIM; kc += 128) {
        for (int t = tid; t < HEADS * 128; t += 256) {
            us[t >> 7][t & 127] = ub[(t >> 7) * DIM + kc + (t & 127)];
        }
        __syncthreads();
        #pragma unroll
        for (int r = 0; r < 4; r++) {
            const __half2* xr = (const __half2*)(g_xhi + (size_t)(row0 + r) * DIM);
            __half2 x01 = xr[(kc >> 1) + lane * 2];
            __half2 x23 = xr[(kc >> 1) + lane * 2 + 1];
            float2 f01 = __half22float2(x01);
            float2 f23 = __half22float2(x23);
            #pragma unroll
            for (int h = 0; h < HEADS; h++) {
                float4 uv = *(const float4*)&us[h][lane * 4];
                acc[r][h] += f01.x * uv.x + f01.y * uv.y + f23.x * uv.z + f23.y * uv.w;
            }
        }
        __syncthreads();
    }
    #pragma unroll
    for (int r = 0; r < 4; r++) {
        int n = (row0 + r) & (SEQ - 1);
        #pragma unroll
        for (int h = 0; h < HEADS; h++) {
            float s = acc[r][h];
            #pragma unroll
            for (int o = 16; o > 0; o >>= 1) s += __shfl_xor_sync(0xffffffffu, s, o);
            if (lane == 0) g_z[((size_t)(b * HEADS + h)) * SEQ + n] = s * SCALE;
        }
    }
}

__global__ void softmax_attn2() {
    int bh = blockIdx.x;
    float* z = g_z + (size_t)bh * SEQ;
    __shared__ float red[256];
    int t = threadIdx.x;
    float m = -1e30f;
    for (int i = t; i < SEQ; i += 256) m = fmaxf(m, z[i]);
    red[t] = m; __syncthreads();
    for (int o = 128; o > 0; o >>= 1) { if (t < o) red[t] = fmaxf(red[t], red[t + o]); __syncthreads(); }
    m = red[0]; __syncthreads();
    float s = 0.f;
    for (int i = t; i < SEQ; i += 256) { float e = __expf(z[i] - m); z[i] = e; s += e; }
    red[t] = s; __syncthreads();
    for (int o = 128; o > 0; o >>= 1) { if (t < o) red[t] += red[t + o]; __syncthreads(); }
    float inv = 1.0f / red[0];
    for (int i = t; i < SEQ; i += 256) z[i] *= inv;
    __syncthreads();
    for (int i = t; i < 4224; i += 256) {
        g_a2hi[bh * 4224 + i] = __float2half_rn(z[i & (SEQ - 1)]);
    }
}

// ---------------- fp16 tensor GEMM: BK=64, cp.async 3-stage ----------------
#define GSTAGE (128 * GPITCH)
__global__ __launch_bounds__(256, 2) void gemm_split(
    const h16* __restrict__ Ahi, const h16* __restrict__ Whi,
    const float* __restrict__ bias, float* __restrict__ C, int mode)
{
    extern __shared__ h16 gsm[];
    h16* As_ = gsm;
    h16* Bs_ = gsm + 3 * GSTAGE;
    const int tid = threadIdx.x;
    const int lane = tid & 31;
    const int wid = tid >> 5;
    const int m0 = blockIdx.y * 128;
    const int n0 = blockIdx.x * 128;
    const int wm = (wid >> 2) * 64;
    const int wn = (wid & 3) * 32;
    const int g = lane >> 2;
    const int t4 = lane & 3;

    float acc[4][4][4];
    #pragma unroll
    for (int i = 0; i < 4; i++)
        #pragma unroll
        for (int j = 0; j < 4; j++)
            #pragma unroll
            for (int k = 0; k < 4; k++) acc[i][j][k] = 0.f;

    const int arow = wm + (lane & 15);
    const int acolsel = (lane >> 4) * 8;
    const int bgrp = lane >> 3;
    const int brow = wn + ((bgrp >> 1) * 8) + (lane & 7);
    const int bcolsel = (bgrp & 1) * 8;

    const int lr = tid >> 3;
    const int lc16 = (tid & 7) * 8;

#define G_ISSUE(st_, s_) do {                                                            \
    const int kk_ = (s_) * 64;                                                           \
    _Pragma("unroll")                                                                    \
    for (int rq_ = 0; rq_ < 4; rq_++) {                                                  \
        const int row_ = lr + rq_ * 32;                                                  \
        unsigned sa_ = smem_u32(As_ + (st_) * GSTAGE + row_ * GPITCH + lc16);            \
        const h16* ga_ = Ahi + (size_t)(m0 + row_) * DIM + kk_ + lc16;                   \
        asm volatile("cp.async.cg.shared.global [%0], [%1], 16;" :: "r"(sa_), "l"(ga_)); \
        unsigned sb_ = smem_u32(Bs_ + (st_) * GSTAGE + row_ * GPITCH + lc16);            \
        const h16* gb_ = Whi + (size_t)(n0 + row_) * DIM + kk_ + lc16;                   \
        asm volatile("cp.async.cg.shared.global [%0], [%1], 16;" :: "r"(sb_), "l"(gb_)); \
    }                                                                                    \
    asm volatile("cp.async.commit_group;");                                              \
} while (0)

    G_ISSUE(0, 0);

    for (int s = 0; s < 16; s++) {
        const int st = s % 3;
        if (s + 1 < 16) {
            G_ISSUE((s + 1) % 3, s + 1);
            asm volatile("cp.async.wait_group 1;");
        } else {
            asm volatile("cp.async.wait_group 0;");
        }
        __syncthreads();
        const h16* Ab = As_ + st * GSTAGE;
        const h16* Bb = Bs_ + st * GSTAGE;
        #pragma unroll
        for (int khb = 0; khb < 64; khb += 16) {
            unsigned af[4][4];
            #pragma unroll
            for (int mi = 0; mi < 4; mi++) {
                ldsm_x4(af[mi][0], af[mi][1], af[mi][2], af[mi][3],
                        smem_u32(Ab + (arow + mi * 16) * GPITCH + khb + acolsel));
            }
            unsigned bfr[4][2];
            #pragma unroll
            for (int p = 0; p < 2; p++) {
                unsigned r0, r1, r2, r3;
                ldsm_x4(r0, r1, r2, r3,
                        smem_u32(Bb + (brow + p * 16) * GPITCH + khb + bcolsel));
                bfr[p * 2 + 0][0] = r0; bfr[p * 2 + 0][1] = r1;
                bfr[p * 2 + 1][0] = r2; bfr[p * 2 + 1][1] = r3;
            }
            #pragma unroll
            for (int mi = 0; mi < 4; mi++)
                #pragma unroll
                for (int ni = 0; ni < 4; ni++)
                    mma_f16(acc[mi][ni], af[mi][0], af[mi][1], af[mi][2], af[mi][3],
                            bfr[ni][0], bfr[ni][1]);
        }
    }
#undef G_ISSUE

    if (mode == 0) {
        #pragma unroll
        for (int mi = 0; mi < 4; mi++) {
            int row = m0 + wm + mi * 16 + g;
            #pragma unroll
            for (int ni = 0; ni < 4; ni++) {
                int col = n0 + wn + ni * 8 + 2 * t4;
                float2 bb = *(const float2*)&bias[col];
                float2 v0 = make_float2(acc[mi][ni][0] + bb.x, acc[mi][ni][1] + bb.y);
                float2 v1 = make_float2(acc[mi][ni][2] + bb.x, acc[mi][ni][3] + bb.y);
                *(float2*)&C[(size_t)row * DIM + col] = v0;
                *(float2*)&C[(size_t)(row + 8) * DIM + col] = v1;
            }
        }
    } else {
        #pragma unroll
        for (int mi = 0; mi < 4; mi++) {
            int row = m0 + wm + mi * 16 + g;
            int b = row >> 11;
            int j = row & (SEQ - 1);
            #pragma unroll
            for (int ni = 0; ni < 4; ni++) {
                int col = n0 + wn + ni * 8 + 2 * t4;
                #pragma unroll
                for (int q = 0; q < 4; q++) {
                    int cc = col + (q & 1);
                    int jj = j + (q >> 1) * 8;
                    size_t idx = (((size_t)(b * HEADS + (cc >> 6))) * HDIM + (cc & 63)) * SEQ + jj;
                    g_vthi[idx] = __float2half_rn(acc[mi][ni][q]);
                }
            }
        }
    }
}

// ---------------- fp16 circular conv, i-tile 256, BK=64 ----------------
__global__ __launch_bounds__(256) void conv_mma() {
    __shared__ unsigned wps[2][320];
    __shared__ h16 Bs[2][64 * CPITCH];
    const int tid = threadIdx.x;
    const int lane = tid & 31;
    const int wid = tid >> 5;
    const int i0 = blockIdx.x * 256;
    const int bh = blockIdx.y;
    const int b = bh >> 4;
    const int h = bh & 15;
    const int wm = (wid >> 1) * 64;
    const int wn = (wid & 1) * 32;
    const int g = lane >> 2;
    const int t4 = lane & 3;

    const unsigned short* a2h = (const unsigned short*)(g_a2hi + (size_t)bh * 4224);
    const h16* vth = g_vthi + (size_t)bh * HDIM * SEQ;

    float acc[4][4][4];
    #pragma unroll
    for (int i = 0; i < 4; i++)
        #pragma unroll
        for (int j = 0; j < 4; j++)
            #pragma unroll
            for (int k = 0; k < 4; k++) acc[i][j][k] = 0.f;

    const int br0 = tid >> 3;
    const int bc16 = (tid & 7) * 8;
    const int bgrp = lane >> 3;
    const int brow = wn + ((bgrp >> 1) * 8) + (lane & 7);
    const int bcolsel = (bgrp & 1) * 8;

    {
        const int ws = 1793 - i0;
        wps[0][tid] = (unsigned)a2h[ws + tid] | ((unsigned)a2h[ws + tid + 1] << 16);
        if (tid < 64) {
            int t2 = tid + 256;
            wps[0][t2] = (unsigned)a2h[ws + t2] | ((unsigned)a2h[ws + t2 + 1] << 16);
        }
        uint4 pb0 = *(const uint4*)(vth + (size_t)br0 * SEQ + bc16);
        uint4 pb1 = *(const uint4*)(vth + (size_t)(br0 + 32) * SEQ + bc16);
        *(uint4*)&Bs[0][br0 * CPITCH + bc16] = pb0;
        *(uint4*)&Bs[0][(br0 + 32) * CPITCH + bc16] = pb1;
    }
    __syncthreads();

    for (int s = 0; s < 32; s++) {
        const int buf = s & 1;
        const int sn = s + 1;
        unsigned wv0 = 0u, wv1 = 0u;
        uint4 bv0, bv1;
        if (sn < 32) {
            const int j0 = sn * 64;
            const int ws = 1793 + j0 - i0;
            wv0 = (unsigned)a2h[ws + tid] | ((unsigned)a2h[ws + tid + 1] << 16);
            if (tid < 64) {
                int t2 = tid + 256;
                wv1 = (unsigned)a2h[ws + t2] | ((unsigned)a2h[ws + t2 + 1] << 16);
            }
            bv0 = *(const uint4*)(vth + (size_t)br0 * SEQ + j0 + bc16);
            bv1 = *(const uint4*)(vth + (size_t)(br0 + 32) * SEQ + j0 + bc16);
        }
        #pragma unroll
        for (int khb = 0; khb < 64; khb += 16) {
            const int ub = 255 - (wm + g) + 2 * t4 + khb;
            unsigned fa0[4], fa1[4], fa2[4];
            #pragma unroll
            for (int mi = 0; mi < 4; mi++) {
                const int u = ub - mi * 16;
                fa0[mi] = wps[buf][u];
                fa1[mi] = wps[buf][u - 8];
                fa2[mi] = wps[buf][u + 8];
            }
            unsigned bfr[4][2];
            #pragma unroll
            for (int p = 0; p < 2; p++) {
                unsigned r0, r1, r2, r3;
                ldsm_x4(r0, r1, r2, r3,
                        smem_u32(&Bs[buf][(brow + p * 16) * CPITCH + khb + bcolsel]));
                bfr[p * 2 + 0][0] = r0; bfr[p * 2 + 0][1] = r1;
                bfr[p * 2 + 1][0] = r2; bfr[p * 2 + 1][1] = r3;
            }
            #pragma unroll
            for (int mi = 0; mi < 4; mi++)
                #pragma unroll
                for (int ni = 0; ni < 4; ni++)
                    mma_f16(acc[mi][ni], fa0[mi], fa1[mi], fa2[mi], fa0[mi],
                            bfr[ni][0], bfr[ni][1]);
        }
        if (sn < 32) {
            const int nb = buf ^ 1;
            wps[nb][tid] = wv0;
            if (tid < 64) wps[nb][tid + 256] = wv1;
            *(uint4*)&Bs[nb][br0 * CPITCH + bc16] = bv0;
            *(uint4*)&Bs[nb][(br0 + 32) * CPITCH + bc16] = bv1;
        }
        __syncthreads();
    }

    #pragma unroll
    for (int mi = 0; mi < 4; mi++) {
        int row = i0 + wm + mi * 16 + g;
        #pragma unroll
        for (int ni = 0; ni < 4; ni++) {
            int col = h * HDIM + wn + ni * 8 + 2 * t4;
            size_t o0 = ((size_t)b * SEQ + row) * DIM + col;
            size_t o1 = ((size_t)b * SEQ + row + 8) * DIM + col;
            *(__half2*)&g_ohhi[o0] = __halves2half2(__float2half_rn(acc[mi][ni][0]),
                                                    __float2half_rn(acc[mi][ni][1]));
            *(__half2*)&g_ohhi[o1] = __halves2half2(__float2half_rn(acc[mi][ni][2]),
                                                    __float2half_rn(acc[mi][ni][3]));
        }
    }
}

// ---------------- launch ----------------
extern "C" void kernel_launch(void* const* d_in, const int* in_sizes, int n_in,
                              void* d_out, int out_size) {
    const float* x  = (const float*)d_in[0];
    const float* wq = (const float*)d_in[1];
    const float* wk = (const float*)d_in[2];
    const float* wv = (const float*)d_in[3];
    const float* wp = (const float*)d_in[4];
    const float* bp = (const float*)d_in[5];
    float* out = (float*)d_out;

    void* p2; cudaGetSymbolAddress(&p2, g_xhi);  h16* xhi  = (h16*)p2;
    void* p4; cudaGetSymbolAddress(&p4, g_wvhi); h16* wvhi = (h16*)p4;
    void* p6; cudaGetSymbolAddress(&p6, g_wphi); h16* wphi = (h16*)p6;
    void* p8; cudaGetSymbolAddress(&p8, g_ohhi); h16* ohhi = (h16*)p8;

    const int gemm_smem = 6 * GSTAGE * (int)sizeof(h16);   // 110592
    cudaFuncSetAttribute(gemm_split, cudaFuncAttributeMaxDynamicSharedMemorySize, gemm_smem);

    // 1: x split + partial column sums
    splitx_colsum<<<dim3(DIM / 256, BATCH, 32), 256>>>(x);
    // 2: weight splits + xavg final reduce
    splitw_xavg<<<2304, 256>>>(wv, wp);
    // 3: v-projection GEMM
    gemm_split<<<dim3(DIM / 128, MTOT / 128), 256, gemm_smem>>>(
        xhi, wvhi, (const float*)0, (float*)0, 1);

    // attention-weight path (batch-fused weight reads)
    kavg2_kernel<<<(DIM * 32) / 256, 256>>>(wk);
    u2_kernel<<<dim3(DIM / 256, HEADS), 256>>>(wq);
    z_kernel3<<<MTOT / 32, 256>>>();
    softmax_attn2<<<BATCH * HEADS, 256>>>();

    // circular conv (i-tile 256)
    conv_mma<<<dim3(SEQ / 256, BATCH * HEADS), 256>>>();

    // output projection with bias
    gemm_split<<<dim3(DIM / 128, MTOT / 128), 256, gemm_smem>>>(ohhi, wphi, bp, out, 0);
}

// round 17
// speedup vs baseline: 1.1809x; 1.0130x over previous
#include <cuda_runtime.h>
#include <cuda_fp16.h>
#include <cstdint>

#define BATCH 2
#define SEQ   2048
#define DIM   1024
#define HEADS 16
#define HDIM  64
#define SCALE 0.125f
#define MTOT  4096
#define GPITCH 72
#define CPITCH 72

typedef __half h16;

// ---------------- scratch ----------------
__device__ float g_partial[BATCH * 32 * DIM];
__device__ float g_xavg[BATCH * DIM];
__device__ float g_kpart[4 * BATCH * DIM];      // [chunk][b][co]
__device__ float g_u[BATCH * HEADS * DIM];
__device__ float g_z[BATCH * HEADS * SEQ];

__device__ h16 g_xhi[(size_t)MTOT * DIM];
__device__ h16 g_wvhi[DIM * DIM];
__device__ h16 g_wphi[DIM * DIM];
__device__ h16 g_vthi[32 * HDIM * SEQ];
__device__ h16 g_a2hi[32 * 4224];
__device__ h16 g_ohhi[(size_t)MTOT * DIM];

// ---------------- PTX helpers ----------------
__device__ __forceinline__ unsigned smem_u32(const void* p) {
    return (unsigned)__cvta_generic_to_shared(p);
}

__device__ __forceinline__ void ldsm_x4(unsigned& r0, unsigned& r1, unsigned& r2, unsigned& r3, unsigned a) {
    asm volatile("ldmatrix.sync.aligned.m8n8.x4.shared.b16 {%0,%1,%2,%3}, [%4];"
                 : "=r"(r0), "=r"(r1), "=r"(r2), "=r"(r3) : "r"(a));
}

__device__ __forceinline__ void mma_f16(float* c, unsigned a0, unsigned a1, unsigned a2, unsigned a3,
                                        unsigned b0, unsigned b1) {
    asm volatile("mma.sync.aligned.m16n8k16.row.col.f32.f16.f16.f32 "
                 "{%0,%1,%2,%3}, {%4,%5,%6,%7}, {%8,%9}, {%0,%1,%2,%3};"
                 : "+f"(c[0]), "+f"(c[1]), "+f"(c[2]), "+f"(c[3])
                 : "r"(a0), "r"(a1), "r"(a2), "r"(a3), "r"(b0), "r"(b1));
}

// ---------------- fused x split + partial column sums ----------------
__global__ void splitx_colsum(const float* __restrict__ x) {
    int c = blockIdx.x * 256 + threadIdx.x;
    int b = blockIdx.y, sz = blockIdx.z;
    const float* xp = x + ((size_t)b * SEQ + (size_t)sz * 64) * DIM + c;
    h16* hp = g_xhi + ((size_t)b * SEQ + (size_t)sz * 64) * DIM + c;
    float sum = 0.f;
    #pragma unroll 8
    for (int n = 0; n < 64; n++) {
        float v = xp[(size_t)n * DIM];
        sum += v;
        hp[(size_t)n * DIM] = __float2half_rn(v);
    }
    g_partial[(b * 32 + sz) * DIM + c] = sum;
}

// fused: weight splits (blocks 0..2047) + xavg final reduce (blocks 2048..2303)
__global__ void splitw_xavg(const float* __restrict__ wv, const float* __restrict__ wp) {
    int bx = blockIdx.x;
    int tid = threadIdx.x;
    if (bx < 2048) {
        int i = (bx & 1023) * 256 + tid;
        const float* in = (bx >= 1024) ? wp : wv;
        h16* hi = (bx >= 1024) ? g_wphi : g_wvhi;
        float4 v = ((const float4*)in)[i];
        __half2* H = (__half2*)hi;
        H[i * 2 + 0] = __halves2half2(__float2half_rn(v.x), __float2half_rn(v.y));
        H[i * 2 + 1] = __halves2half2(__float2half_rn(v.z), __float2half_rn(v.w));
    } else {
        int w = ((bx - 2048) * 256 + tid) >> 5;   // 0..2047
        int lane = tid & 31;
        int b = w >> 10, c = w & (DIM - 1);
        float s = g_partial[(b * 32 + lane) * DIM + c];
        #pragma unroll
        for (int o = 16; o > 0; o >>= 1) s += __shfl_xor_sync(0xffffffffu, s, o);
        if (lane == 0) g_xavg[b * DIM + c] = s * (1.0f / SEQ);
    }
}

// split-K kavg: 4096 warps, float4 loads; partials to g_kpart
__global__ void kavg_part(const float* __restrict__ wk) {
    int w = (blockIdx.x * 256 + threadIdx.x) >> 5;   // 0..4095
    int lane = threadIdx.x & 31;
    int co = w >> 2;
    int ch = w & 3;
    int cbase = ch * 256;
    const float* wr = wk + (size_t)co * DIM + cbase;
    const float* xa0 = g_xavg + cbase;
    const float* xa1 = g_xavg + DIM + cbase;
    float s0 = 0.f, s1 = 0.f;
    #pragma unroll
    for (int it = 0; it < 2; it++) {
        int c = it * 128 + lane * 4;
        float4 wv4 = *(const float4*)(wr + c);
        float4 a0 = *(const float4*)(xa0 + c);
        float4 a1 = *(const float4*)(xa1 + c);
        s0 += wv4.x * a0.x + wv4.y * a0.y + wv4.z * a0.z + wv4.w * a0.w;
        s1 += wv4.x * a1.x + wv4.y * a1.y + wv4.z * a1.z + wv4.w * a1.w;
    }
    #pragma unroll
    for (int o = 16; o > 0; o >>= 1) {
        s0 += __shfl_xor_sync(0xffffffffu, s0, o);
        s1 += __shfl_xor_sync(0xffffffffu, s1, o);
    }
    if (lane == 0) {
        g_kpart[(ch * BATCH + 0) * DIM + co] = s0;
        g_kpart[(ch * BATCH + 1) * DIM + co] = s1;
    }
}

// u for BOTH batches per block; reduces kavg partials in-block
__global__ void u2_kernel(const float* __restrict__ wq) {
    int c = blockIdx.x * 256 + threadIdx.x;
    int h = blockIdx.y;
    __shared__ float ka[2][HDIM];
    if (threadIdx.x < 2 * HDIM) {
        int b = threadIdx.x >> 6, d = threadIdx.x & 63;
        int co = h * HDIM + d;
        float s = g_kpart[(0 * BATCH + b) * DIM + co]
                + g_kpart[(1 * BATCH + b) * DIM + co]
                + g_kpart[(2 * BATCH + b) * DIM + co]
                + g_kpart[(3 * BATCH + b) * DIM + co];
        ka[b][d] = s;
    }
    __syncthreads();
    float s0 = 0.f, s1 = 0.f;
    #pragma unroll
    for (int d = 0; d < HDIM; d++) {
        float w = wq[(size_t)(h * HDIM + d) * DIM + c];
        s0 += ka[0][d] * w;
        s1 += ka[1][d] * w;
    }
    g_u[(size_t)h * DIM + c] = s0;
    g_u[((size_t)HEADS + h) * DIM + c] = s1;
}

// z: 32 rows per block (4 rows per warp)
__global__ __launch_bounds__(256) void z_kernel3() {
    __shared__ float us[HEADS][132];
    int tid = threadIdx.x, lane = tid & 31, w = tid >> 5;
    int row0 = blockIdx.x * 32 + w * 4;
    int b = row0 >> 11;
    const float* ub = g_u + (size_t)b * HEADS * DIM;

    float acc[4][HEADS];
    #pragma unroll
    for (int r = 0; r < 4; r++)
        #pragma unroll
        for (int h = 0; h < HEADS; h++) acc[r][h] = 0.f;

    for (int kc = 0; kc < DIM; kc += 128) {
        for (int t = tid; t < HEADS * 128; t += 256) {
            us[t >> 7][t & 127] = ub[(t >> 7) * DIM + kc + (t & 127)];
        }
        __syncthreads();
        #pragma unroll
        for (int r = 0; r < 4; r++) {
            const __half2* xr = (const __half2*)(g_xhi + (size_t)(row0 + r) * DIM);
            __half2 x01 = xr[(kc >> 1) + lane * 2];
            __half2 x23 = xr[(kc >> 1) + lane * 2 + 1];
            float2 f01 = __half22float2(x01);
            float2 f23 = __half22float2(x23);
            #pragma unroll
            for (int h = 0; h < HEADS; h++) {
                float4 uv = *(const float4*)&us[h][lane * 4];
                acc[r][h] += f01.x * uv.x + f01.y * uv.y + f23.x * uv.z + f23.y * uv.w;
            }
        }
        __syncthreads();
    }
    #pragma unroll
    for (int r = 0; r < 4; r++) {
        int n = (row0 + r) & (SEQ - 1);
        #pragma unroll
        for (int h = 0; h < HEADS; h++) {
            float s = acc[r][h];
            #pragma unroll
            for (int o = 16; o > 0; o >>= 1) s += __shfl_xor_sync(0xffffffffu, s, o);
            if (lane == 0) g_z[((size_t)(b * HEADS + h)) * SEQ + n] = s * SCALE;
        }
    }
}

__global__ void softmax_attn2() {
    int bh = blockIdx.x;
    float* z = g_z + (size_t)bh * SEQ;
    __shared__ float red[256];
    int t = threadIdx.x;
    float m = -1e30f;
    for (int i = t; i < SEQ; i += 256) m = fmaxf(m, z[i]);
    red[t] = m; __syncthreads();
    for (int o = 128; o > 0; o >>= 1) { if (t < o) red[t] = fmaxf(red[t], red[t + o]); __syncthreads(); }
    m = red[0]; __syncthreads();
    float s = 0.f;
    for (int i = t; i < SEQ; i += 256) { float e = __expf(z[i] - m); z[i] = e; s += e; }
    red[t] = s; __syncthreads();
    for (int o = 128; o > 0; o >>= 1) { if (t < o) red[t] += red[t + o]; __syncthreads(); }
    float inv = 1.0f / red[0];
    for (int i = t; i < SEQ; i += 256) z[i] *= inv;
    __syncthreads();
    for (int i = t; i < 4224; i += 256) {
        g_a2hi[bh * 4224 + i] = __float2half_rn(z[i & (SEQ - 1)]);
    }
}

// ---------------- fp16 tensor GEMM: BK=64, cp.async 3-stage ----------------
#define GSTAGE (128 * GPITCH)
__global__ __launch_bounds__(256, 2) void gemm_split(
    const h16* __restrict__ Ahi, const h16* __restrict__ Whi,
    const float* __restrict__ bias, float* __restrict__ C, int mode)
{
    extern __shared__ h16 gsm[];
    h16* As_ = gsm;
    h16* Bs_ = gsm + 3 * GSTAGE;
    const int tid = threadIdx.x;
    const int lane = tid & 31;
    const int wid = tid >> 5;
    const int m0 = blockIdx.y * 128;
    const int n0 = blockIdx.x * 128;
    const int wm = (wid >> 2) * 64;
    const int wn = (wid & 3) * 32;
    const int g = lane >> 2;
    const int t4 = lane & 3;

    float acc[4][4][4];
    #pragma unroll
    for (int i = 0; i < 4; i++)
        #pragma unroll
        for (int j = 0; j < 4; j++)
            #pragma unroll
            for (int k = 0; k < 4; k++) acc[i][j][k] = 0.f;

    const int arow = wm + (lane & 15);
    const int acolsel = (lane >> 4) * 8;
    const int bgrp = lane >> 3;
    const int brow = wn + ((bgrp >> 1) * 8) + (lane & 7);
    const int bcolsel = (bgrp & 1) * 8;

    const int lr = tid >> 3;
    const int lc16 = (tid & 7) * 8;

#define G_ISSUE(st_, s_) do {                                                            \
    const int kk_ = (s_) * 64;                                                           \
    _Pragma("unroll")                                                                    \
    for (int rq_ = 0; rq_ < 4; rq_++) {                                                  \
        const int row_ = lr + rq_ * 32;                                                  \
        unsigned sa_ = smem_u32(As_ + (st_) * GSTAGE + row_ * GPITCH + lc16);            \
        const h16* ga_ = Ahi + (size_t)(m0 + row_) * DIM + kk_ + lc16;                   \
        asm volatile("cp.async.cg.shared.global [%0], [%1], 16;" :: "r"(sa_), "l"(ga_)); \
        unsigned sb_ = smem_u32(Bs_ + (st_) * GSTAGE + row_ * GPITCH + lc16);            \
        const h16* gb_ = Whi + (size_t)(n0 + row_) * DIM + kk_ + lc16;                   \
        asm volatile("cp.async.cg.shared.global [%0], [%1], 16;" :: "r"(sb_), "l"(gb_)); \
    }                                                                                    \
    asm volatile("cp.async.commit_group;");                                              \
} while (0)

    G_ISSUE(0, 0);

    for (int s = 0; s < 16; s++) {
        const int st = s % 3;
        if (s + 1 < 16) {
            G_ISSUE((s + 1) % 3, s + 1);
            asm volatile("cp.async.wait_group 1;");
        } else {
            asm volatile("cp.async.wait_group 0;");
        }
        __syncthreads();
        const h16* Ab = As_ + st * GSTAGE;
        const h16* Bb = Bs_ + st * GSTAGE;
        #pragma unroll
        for (int khb = 0; khb < 64; khb += 16) {
            unsigned af[4][4];
            #pragma unroll
            for (int mi = 0; mi < 4; mi++) {
                ldsm_x4(af[mi][0], af[mi][1], af[mi][2], af[mi][3],
                        smem_u32(Ab + (arow + mi * 16) * GPITCH + khb + acolsel));
            }
            unsigned bfr[4][2];
            #pragma unroll
            for (int p = 0; p < 2; p++) {
                unsigned r0, r1, r2, r3;
                ldsm_x4(r0, r1, r2, r3,
                        smem_u32(Bb + (brow + p * 16) * GPITCH + khb + bcolsel));
                bfr[p * 2 + 0][0] = r0; bfr[p * 2 + 0][1] = r1;
                bfr[p * 2 + 1][0] = r2; bfr[p * 2 + 1][1] = r3;
            }
            #pragma unroll
            for (int mi = 0; mi < 4; mi++)
                #pragma unroll
                for (int ni = 0; ni < 4; ni++)
                    mma_f16(acc[mi][ni], af[mi][0], af[mi][1], af[mi][2], af[mi][3],
                            bfr[ni][0], bfr[ni][1]);
        }
    }
#undef G_ISSUE

    if (mode == 0) {
        #pragma unroll
        for (int mi = 0; mi < 4; mi++) {
            int row = m0 + wm + mi * 16 + g;
            #pragma unroll
            for (int ni = 0; ni < 4; ni++) {
                int col = n0 + wn + ni * 8 + 2 * t4;
                float2 bb = *(const float2*)&bias[col];
                float2 v0 = make_float2(acc[mi][ni][0] + bb.x, acc[mi][ni][1] + bb.y);
                float2 v1 = make_float2(acc[mi][ni][2] + bb.x, acc[mi][ni][3] + bb.y);
                *(float2*)&C[(size_t)row * DIM + col] = v0;
                *(float2*)&C[(size_t)(row + 8) * DIM + col] = v1;
            }
        }
    } else {
        #pragma unroll
        for (int mi = 0; mi < 4; mi++) {
            int row = m0 + wm + mi * 16 + g;
            int b = row >> 11;
            int j = row & (SEQ - 1);
            #pragma unroll
            for (int ni = 0; ni < 4; ni++) {
                int col = n0 + wn + ni * 8 + 2 * t4;
                #pragma unroll
                for (int q = 0; q < 4; q++) {
                    int cc = col + (q & 1);
                    int jj = j + (q >> 1) * 8;
                    size_t idx = (((size_t)(b * HEADS + (cc >> 6))) * HDIM + (cc & 63)) * SEQ + jj;
                    g_vthi[idx] = __float2half_rn(acc[mi][ni][q]);
                }
            }
        }
    }
}

// ---------------- fp16 circular conv, i-tile 256, BK=64 ----------------
__global__ __launch_bounds__(256) void conv_mma() {
    __shared__ unsigned wps[2][320];
    __shared__ h16 Bs[2][64 * CPITCH];
    const int tid = threadIdx.x;
    const int lane = tid & 31;
    const int wid = tid >> 5;
    const int i0 = blockIdx.x * 256;
    const int bh = blockIdx.y;
    const int b = bh >> 4;
    const int h = bh & 15;
    const int wm = (wid >> 1) * 64;
    const int wn = (wid & 1) * 32;
    const int g = lane >> 2;
    const int t4 = lane & 3;

    const unsigned short* a2h = (const unsigned short*)(g_a2hi + (size_t)bh * 4224);
    const h16* vth = g_vthi + (size_t)bh * HDIM * SEQ;

    float acc[4][4][4];
    #pragma unroll
    for (int i = 0; i < 4; i++)
        #pragma unroll
        for (int j = 0; j < 4; j++)
            #pragma unroll
            for (int k = 0; k < 4; k++) acc[i][j][k] = 0.f;

    const int br0 = tid >> 3;
    const int bc16 = (tid & 7) * 8;
    const int bgrp = lane >> 3;
    const int brow = wn + ((bgrp >> 1) * 8) + (lane & 7);
    const int bcolsel = (bgrp & 1) * 8;

    {
        const int ws = 1793 - i0;
        wps[0][tid] = (unsigned)a2h[ws + tid] | ((unsigned)a2h[ws + tid + 1] << 16);
        if (tid < 64) {
            int t2 = tid + 256;
            wps[0][t2] = (unsigned)a2h[ws + t2] | ((unsigned)a2h[ws + t2 + 1] << 16);
        }
        uint4 pb0 = *(const uint4*)(vth + (size_t)br0 * SEQ + bc16);
        uint4 pb1 = *(const uint4*)(vth + (size_t)(br0 + 32) * SEQ + bc16);
        *(uint4*)&Bs[0][br0 * CPITCH + bc16] = pb0;
        *(uint4*)&Bs[0][(br0 + 32) * CPITCH + bc16] = pb1;
    }
    __syncthreads();

    for (int s = 0; s < 32; s++) {
        const int buf = s & 1;
        const int sn = s + 1;
        unsigned wv0 = 0u, wv1 = 0u;
        uint4 bv0, bv1;
        if (sn < 32) {
            const int j0 = sn * 64;
            const int ws = 1793 + j0 - i0;
            wv0 = (unsigned)a2h[ws + tid] | ((unsigned)a2h[ws + tid + 1] << 16);
            if (tid < 64) {
                int t2 = tid + 256;
                wv1 = (unsigned)a2h[ws + t2] | ((unsigned)a2h[ws + t2 + 1] << 16);
            }
            bv0 = *(const uint4*)(vth + (size_t)br0 * SEQ + j0 + bc16);
            bv1 = *(const uint4*)(vth + (size_t)(br0 + 32) * SEQ + j0 + bc16);
        }
        #pragma unroll
        for (int khb = 0; khb < 64; khb += 16) {
            const int ub = 255 - (wm + g) + 2 * t4 + khb;
            unsigned fa0[4], fa1[4], fa2[4];
            #pragma unroll
            for (int mi = 0; mi < 4; mi++) {
                const int u = ub - mi * 16;
                fa0[mi] = wps[buf][u];
                fa1[mi] = wps[buf][u - 8];
                fa2[mi] = wps[buf][u + 8];
            }
            unsigned bfr[4][2];
            #pragma unroll
            for (int p = 0; p < 2; p++) {
                unsigned r0, r1, r2, r3;
                ldsm_x4(r0, r1, r2, r3,
                        smem_u32(&Bs[buf][(brow + p * 16) * CPITCH + khb + bcolsel]));
                bfr[p * 2 + 0][0] = r0; bfr[p * 2 + 0][1] = r1;
                bfr[p * 2 + 1][0] = r2; bfr[p * 2 + 1][1] = r3;
            }
            #pragma unroll
            for (int mi = 0; mi < 4; mi++)
                #pragma unroll
                for (int ni = 0; ni < 4; ni++)
                    mma_f16(acc[mi][ni], fa0[mi], fa1[mi], fa2[mi], fa0[mi],
                            bfr[ni][0], bfr[ni][1]);
        }
        if (sn < 32) {
            const int nb = buf ^ 1;
            wps[nb][tid] = wv0;
            if (tid < 64) wps[nb][tid + 256] = wv1;
            *(uint4*)&Bs[nb][br0 * CPITCH + bc16] = bv0;
            *(uint4*)&Bs[nb][(br0 + 32) * CPITCH + bc16] = bv1;
        }
        __syncthreads();
    }

    #pragma unroll
    for (int mi = 0; mi < 4; mi++) {
        int row = i0 + wm + mi * 16 + g;
        #pragma unroll
        for (int ni = 0; ni < 4; ni++) {
            int col = h * HDIM + wn + ni * 8 + 2 * t4;
            size_t o0 = ((size_t)b * SEQ + row) * DIM + col;
            size_t o1 = ((size_t)b * SEQ + row + 8) * DIM + col;
            *(__half2*)&g_ohhi[o0] = __halves2half2(__float2half_rn(acc[mi][ni][0]),
                                                    __float2half_rn(acc[mi][ni][1]));
            *(__half2*)&g_ohhi[o1] = __halves2half2(__float2half_rn(acc[mi][ni][2]),
                                                    __float2half_rn(acc[mi][ni][3]));
        }
    }
}

// ---------------- launch ----------------
extern "C" void kernel_launch(void* const* d_in, const int* in_sizes, int n_in,
                              void* d_out, int out_size) {
    const float* x  = (const float*)d_in[0];
    const float* wq = (const float*)d_in[1];
    const float* wk = (const float*)d_in[2];
    const float* wv = (const float*)d_in[3];
    const float* wp = (const float*)d_in[4];
    const float* bp = (const float*)d_in[5];
    float* out = (float*)d_out;

    void* p2; cudaGetSymbolAddress(&p2, g_xhi);  h16* xhi  = (h16*)p2;
    void* p4; cudaGetSymbolAddress(&p4, g_wvhi); h16* wvhi = (h16*)p4;
    void* p6; cudaGetSymbolAddress(&p6, g_wphi); h16* wphi = (h16*)p6;
    void* p8; cudaGetSymbolAddress(&p8, g_ohhi); h16* ohhi = (h16*)p8;

    const int gemm_smem = 6 * GSTAGE * (int)sizeof(h16);   // 110592
    cudaFuncSetAttribute(gemm_split, cudaFuncAttributeMaxDynamicSharedMemorySize, gemm_smem);

    // 1: x split + partial column sums
    splitx_colsum<<<dim3(DIM / 256, BATCH, 32), 256>>>(x);
    // 2: weight splits + xavg final reduce
    splitw_xavg<<<2304, 256>>>(wv, wp);
    // 3: v-projection GEMM
    gemm_split<<<dim3(DIM / 128, MTOT / 128), 256, gemm_smem>>>(
        xhi, wvhi, (const float*)0, (float*)0, 1);

    // attention-weight path (split-K kavg; reduction folded into u2)
    kavg_part<<<512, 256>>>(wk);
    u2_kernel<<<dim3(DIM / 256, HEADS), 256>>>(wq);
    z_kernel3<<<MTOT / 32, 256>>>();
    softmax_attn2<<<BATCH * HEADS, 256>>>();

    // circular conv (i-tile 256)
    conv_mma<<<dim3(SEQ / 256, BATCH * HEADS), 256>>>();

    // output projection with bias
    gemm_split<<<dim3(DIM / 128, MTOT / 128), 256, gemm_smem>>>(ohhi, wphi, bp, out, 0);
}